// round 13
// baseline (speedup 1.0000x reference)
#include <cuda_runtime.h>
#include <cuda_fp16.h>
#include <math.h>

#define T_  4
#define N_  400
#define S_  395
#define D_  128
#define H0_ 256
#define H1_ 128
#define GD_ 768
#define TNROWS (T_*N_)           // 1600

// output layout: [wl_mean (400*768)] [learned_score (4*400*400)] [query^T (4*5*400)]
#define OUT_SCORE (N_*GD_)               // 307200
#define OUT_QS    (OUT_SCORE + T_*N_*N_) // 947200

#define ROWH 264                 // padded half-row stride for k_pair ldmatrix tiles

__device__ __half g_ABh[TNROWS*H0_];     // fp16(A + b1)
__device__ __half g_Bh [TNROWS*H0_];     // fp16(B)
__device__ __half g_W2h[H1_*H0_];        // fp16(fc1_w2)
__device__ __half g_ladjH[T_*N_*N_];     // fp16(learned_adj)
__device__ __half g_supH[TNROWS*GD_];
__device__ __half g_supL[TNROWS*GD_];
__device__ float  g_wl[TNROWS*GD_];
__device__ float  g_h2a[TNROWS*H1_];
__device__ float  g_h2b[TNROWS*H1_];

__device__ __forceinline__ float sigmoidf_(float x){ return 1.0f/(1.0f + __expf(-x)); }

__device__ __forceinline__ unsigned smem_u32(const void* p){
    unsigned a;
    asm("{ .reg .u64 t; cvta.to.shared.u64 t, %1; cvt.u32.u64 %0, t; }" : "=r"(a) : "l"(p));
    return a;
}
__device__ __forceinline__ void ldsm_x4(unsigned* r, unsigned addr){
    asm volatile("ldmatrix.sync.aligned.m8n8.x4.shared.b16 {%0,%1,%2,%3}, [%4];"
        : "=r"(r[0]), "=r"(r[1]), "=r"(r[2]), "=r"(r[3]) : "r"(addr));
}
__device__ __forceinline__ void ldsm_x4_t(unsigned* r, unsigned addr){
    asm volatile("ldmatrix.sync.aligned.m8n8.x4.trans.shared.b16 {%0,%1,%2,%3}, [%4];"
        : "=r"(r[0]), "=r"(r[1]), "=r"(r[2]), "=r"(r[3]) : "r"(addr));
}
__device__ __forceinline__ void mma16816(float* d, const unsigned* a, const unsigned* b){
    asm volatile("mma.sync.aligned.m16n8k16.row.col.f32.f16.f16.f32 "
        "{%0,%1,%2,%3},{%4,%5,%6,%7},{%8,%9},{%0,%1,%2,%3};"
        : "+f"(d[0]), "+f"(d[1]), "+f"(d[2]), "+f"(d[3])
        : "r"(a[0]), "r"(a[1]), "r"(a[2]), "r"(a[3]), "r"(b[0]), "r"(b[1]));
}
__device__ __forceinline__ void split2(float x, __half& h, __half& l){
    h = __float2half_rn(x);
    l = __float2half_rn(x - __half2float(h));
}
__device__ __forceinline__ void mma_m16n32_t(float d[4][4], unsigned Asu, unsigned Bsu,
                                             int lane, int warp_m, int warp_n, int PA, int PB)
{
    int ar = lane & 15, ac = (lane >> 4) * 8;
    int bk = ((lane >> 3) & 1) * 8 + (lane & 7);
    int bj = ((lane >> 4) & 1) * 8;
    #pragma unroll
    for (int ks = 0; ks < 4; ks++){
        unsigned a[4], b[2][4];
        ldsm_x4(a, Asu + (unsigned)(((warp_m*16 + ar)*PA + ks*16 + ac)*2));
        #pragma unroll
        for (int nb = 0; nb < 2; nb++)
            ldsm_x4_t(b[nb], Bsu + (unsigned)(((ks*16 + bk)*PB + warp_n*32 + nb*16 + bj)*2));
        #pragma unroll
        for (int nb = 0; nb < 2; nb++){
            mma16816(d[nb*2+0], a, &b[nb][0]);
            mma16816(d[nb*2+1], a, &b[nb][2]);
        }
    }
}
__device__ __forceinline__ void mma_m16n32_n(float d[4][4], unsigned Asu, unsigned Bsu,
                                             int lane, int warp_m, int warp_n, int PA, int PB)
{
    int ar = lane & 15, ac = (lane >> 4) * 8;
    int bg = lane >> 3;
    int bj = ((bg >= 2) ? 8 : 0) + (lane & 7);
    int bk2 = (bg & 1) * 8;
    #pragma unroll
    for (int ks = 0; ks < 4; ks++){
        unsigned a[4], b[2][4];
        ldsm_x4(a, Asu + (unsigned)(((warp_m*16 + ar)*PA + ks*16 + ac)*2));
        #pragma unroll
        for (int nb = 0; nb < 2; nb++)
            ldsm_x4(b[nb], Bsu + (unsigned)(((warp_n*32 + nb*16 + bj)*PB + ks*16 + bk2)*2));
        #pragma unroll
        for (int nb = 0; nb < 2; nb++){
            mma16816(d[nb*2+0], a, &b[nb][0]);
            mma16816(d[nb*2+1], a, &b[nb][2]);
        }
    }
}

// ---------------------------------------------------------------------------
// Kernel 1: A/B precompute (GEMM, fp32 SIMT) -> fp16 g_ABh (A+b1), g_Bh
// ---------------------------------------------------------------------------
__global__ void k_pre(const float* __restrict__ nf, const float* __restrict__ w1,
                      const float* __restrict__ b1)
{
    __shared__ float As[16][64];
    __shared__ float Bs[16][64];
    int tid = threadIdx.x;
    int m0 = blockIdx.y*64, h0 = blockIdx.x*64;
    int tx = tid & 15, ty = tid >> 4;
    float acc[4][4] = {};
    for (int k0 = 0; k0 < D_; k0 += 16){
        #pragma unroll
        for (int i = 0; i < 4; i++){
            int e = i*256 + tid;
            int r = e >> 4, kk = e & 15;
            As[kk][r] = nf[(m0 + r)*D_ + k0 + kk];
        }
        {
            int o  = tid >> 2;
            int kq = (tid & 3)*4;
            int hp = h0 + o;
            const float* src = w1 + (hp & 255)*(2*D_) + (hp >> 8)*D_ + k0 + kq;
            float4 w = *(const float4*)src;
            Bs[kq+0][o] = w.x; Bs[kq+1][o] = w.y; Bs[kq+2][o] = w.z; Bs[kq+3][o] = w.w;
        }
        __syncthreads();
        #pragma unroll
        for (int kk = 0; kk < 16; kk++){
            float ra[4], rb[4];
            #pragma unroll
            for (int i = 0; i < 4; i++) ra[i] = As[kk][ty*4 + i];
            #pragma unroll
            for (int jj = 0; jj < 4; jj++) rb[jj] = Bs[kk][tx*4 + jj];
            #pragma unroll
            for (int i = 0; i < 4; i++)
                #pragma unroll
                for (int jj = 0; jj < 4; jj++)
                    acc[i][jj] += ra[i]*rb[jj];
        }
        __syncthreads();
    }
    #pragma unroll
    for (int i = 0; i < 4; i++)
        #pragma unroll
        for (int jj = 0; jj < 4; jj++){
            int hp = h0 + tx*4 + jj;
            int row = m0 + ty*4 + i;
            float v = acc[i][jj];
            if (hp < H0_) g_ABh[row*H0_ + hp]         = __float2half_rn(v + b1[hp]);
            else          g_Bh [row*H0_ + (hp - 256)] = __float2half_rn(v);
        }
}

// ---------------------------------------------------------------------------
// Kernel 1b: W2 -> fp16 once
// ---------------------------------------------------------------------------
__global__ void k_w2h(const float* __restrict__ w2)
{
    int i = blockIdx.x*256 + threadIdx.x;
    if (i < H1_*H0_) g_W2h[i] = __float2half_rn(w2[i]);
}

// ---------------------------------------------------------------------------
// Kernel 2: pairwise MLP. 2 'a' rows/block, double-buffered h1, builds for the
// next GEMM interleaved into the MMA k-loop (no fragment guards). Full tiles
// b0={0,128,256} pipelined; m16 tail at b0=384.
// ---------------------------------------------------------------------------
__device__ __forceinline__ void pair_build_g(__half* buf, const __half* Ar,
                                             const __half* gB, int i, int tid)
{
    int idx = i*256 + tid;
    int row = idx >> 5, c8 = idx & 31;
    uint4 v = *(const uint4*)&gB[(size_t)row*H0_ + c8*8];
    const __half2 z2 = __float2half2_rn(0.f);
    const __half2* vp = (const __half2*)&v;
    uint4 o; __half2* op = (__half2*)&o;
    #pragma unroll
    for (int q = 0; q < 4; q++)
        op[q] = __hmax2(__hadd2(vp[q], *(const __half2*)&Ar[c8*8 + q*2]), z2);
    *(uint4*)&buf[row*ROWH + c8*8] = o;
}

__global__ void __launch_bounds__(256, 1)
k_pair(const float* __restrict__ b2v, const float* __restrict__ w3,
       const float* __restrict__ b3v, float* __restrict__ score_out)
{
    extern __shared__ char smraw[];
    __half* buf0 = (__half*)smraw;                // 128*ROWH
    __half* buf1 = buf0 + 128*ROWH;               // 128*ROWH
    __half* W2s  = buf1 + 128*ROWH;               // 128*ROWH
    __half* Ar0  = W2s + 128*ROWH;                // 256
    __half* Ar1  = Ar0 + H0_;                     // 256
    float*  sred = (float*)(Ar1 + H0_);           // 128
    float*  b2s  = sred + H1_;                    // 128
    float*  w3s  = b2s + H1_;                     // 128

    int a0 = blockIdx.x*2, a1 = a0 + 1;
    int t  = a0 / N_;
    int tid = threadIdx.x, lane = tid & 31, wid = tid >> 5;
    int warp_n = wid & 3, warp_m = wid >> 2;

    // stage W2 (fp16 copy), A rows, biases
    #pragma unroll
    for (int i = 0; i < 16; i++){
        int idx = i*256 + tid;
        int row = idx >> 5, c8 = idx & 31;
        *(uint4*)&W2s[row*ROWH + c8*8] = *(const uint4*)&g_W2h[row*H0_ + c8*8];
    }
    Ar0[tid] = g_ABh[a0*H0_ + tid];
    Ar1[tid] = g_ABh[a1*H0_ + tid];
    if (tid < H1_){ b2s[tid] = b2v[tid]; w3s[tid] = w3[tid]; sred[tid] = 0.f; }
    float b3 = b3v[0];
    __syncthreads();   // Ars/W2s/biases visible before first build

    unsigned bufu[2] = { smem_u32(buf0), smem_u32(buf1) };
    __half*  bufp[2] = { buf0, buf1 };
    unsigned w2u = smem_u32(W2s);

    int a_trow  = lane & 15;
    int a_tcol8 = (lane >> 4) * 8;
    int b_g     = lane >> 3;
    int b_joff  = ((b_g >= 2) ? 8 : 0) + (lane & 7);
    int b_koff  = (b_g & 1) * 8;

    unsigned aOff[4], bA[2];
    #pragma unroll
    for (int mt = 0; mt < 4; mt++)
        aOff[mt] = (unsigned)(((warp_m*64 + mt*16 + a_trow)*ROWH + a_tcol8)*2);
    #pragma unroll
    for (int nb = 0; nb < 2; nb++)
        bA[nb] = w2u + ((warp_n*32 + nb*16 + b_joff)*ROWH + b_koff)*2;

    // initial build: (tile0, a0) -> buf0
    {
        const __half* gB = &g_Bh[(size_t)(t*N_)*H0_];
        #pragma unroll
        for (int i = 0; i < 16; i++) pair_build_g(buf0, Ar0, gB, i, tid);
    }
    __syncthreads();

    int cur = 0;
    // ======== 6 pipelined full GEMMs: steps (tile,a) = (0,0)..(2,1) ========
    for (int step = 0; step < 6; step++){
        int b0    = (step >> 1) * 128;
        int arow  = ((step & 1) ? a1 : a0);

        // next-build params (runtime, but only gate smem-store code)
        const __half* nAr; const __half* ngB; int niters;
        if (step < 5){
            int ns = step + 1;
            nAr = (ns & 1) ? Ar1 : Ar0;
            ngB = &g_Bh[(size_t)(t*N_ + (ns >> 1)*128)*H0_];
            niters = 16;
        } else {
            nAr = Ar0;
            ngB = &g_Bh[(size_t)(t*N_ + 384)*H0_];
            niters = 2;          // tail tile: 16 rows
        }
        __half* nbuf = bufp[cur ^ 1];
        unsigned curu = bufu[cur];

        float d[4][4][4];
        #pragma unroll
        for (int i=0;i<4;i++)
            #pragma unroll
            for (int j=0;j<4;j++)
                #pragma unroll
                for (int v=0;v<4;v++) d[i][j][v]=0.f;

        #pragma unroll 4
        for (int ks = 0; ks < 16; ks++){
            unsigned afr[4][4], bfr[2][4];
            #pragma unroll
            for (int mt = 0; mt < 4; mt++) ldsm_x4(afr[mt], curu + aOff[mt] + ks*32);
            #pragma unroll
            for (int nb = 0; nb < 2; nb++) ldsm_x4(bfr[nb], bA[nb] + ks*32);
            #pragma unroll
            for (int mt = 0; mt < 4; mt++)
                #pragma unroll
                for (int nb = 0; nb < 2; nb++){
                    mma16816(d[mt][nb*2+0], afr[mt], &bfr[nb][0]);
                    mma16816(d[mt][nb*2+1], afr[mt], &bfr[nb][2]);
                }
            if (ks < niters) pair_build_g(nbuf, nAr, ngB, ks, tid);
        }
        __syncthreads();   // next build visible; cur-buffer reads done

        #pragma unroll
        for (int mt = 0; mt < 4; mt++){
            #pragma unroll
            for (int h = 0; h < 2; h++){
                float part = 0.f;
                #pragma unroll
                for (int n8 = 0; n8 < 4; n8++){
                    #pragma unroll
                    for (int c = 0; c < 2; c++){
                        int j = warp_n*32 + n8*8 + (lane & 3)*2 + c;
                        part += fmaxf(d[mt][n8][h*2 + c] + b2s[j], 0.f) * w3s[j];
                    }
                }
                part += __shfl_xor_sync(0xffffffff, part, 1);
                part += __shfl_xor_sync(0xffffffff, part, 2);
                if ((lane & 3) == 0)
                    atomicAdd(&sred[warp_m*64 + mt*16 + (lane >> 2) + h*8], part);
            }
        }
        __syncthreads();
        if (tid < H1_){
            score_out[arow*N_ + b0 + tid] = sigmoidf_(sred[tid] + b3);
            sred[tid] = 0.f;
        }
        cur ^= 1;
    }

    // ======== tail tile b0 = 384, 16 valid rows (m16 GEMM) ========
    {
        const int b0 = 384;
        unsigned curu = bufu[cur];      // tail-a0 h1 built during step 5

        // ---- m16 GEMM + epilogue for a0 (warp_m==0 only; fully unrolled) ----
        if (warp_m == 0){
            float d[4][4];
            #pragma unroll
            for (int j=0;j<4;j++)
                #pragma unroll
                for (int v=0;v<4;v++) d[j][v]=0.f;
            #pragma unroll 4
            for (int ks = 0; ks < 16; ks++){
                unsigned afr[4], bfr[2][4];
                ldsm_x4(afr, curu + ((a_trow)*ROWH + a_tcol8)*2 + ks*32);
                #pragma unroll
                for (int nb = 0; nb < 2; nb++) ldsm_x4(bfr[nb], bA[nb] + ks*32);
                #pragma unroll
                for (int nb = 0; nb < 2; nb++){
                    mma16816(d[nb*2+0], afr, &bfr[nb][0]);
                    mma16816(d[nb*2+1], afr, &bfr[nb][2]);
                }
            }
            #pragma unroll
            for (int h = 0; h < 2; h++){
                float part = 0.f;
                #pragma unroll
                for (int n8 = 0; n8 < 4; n8++){
                    #pragma unroll
                    for (int c = 0; c < 2; c++){
                        int j = warp_n*32 + n8*8 + (lane & 3)*2 + c;
                        part += fmaxf(d[n8][h*2 + c] + b2s[j], 0.f) * w3s[j];
                    }
                }
                part += __shfl_xor_sync(0xffffffff, part, 1);
                part += __shfl_xor_sync(0xffffffff, part, 2);
                if ((lane & 3) == 0)
                    atomicAdd(&sred[(lane >> 2) + h*8], part);
            }
        }
        // meanwhile: all threads also build tail-a1 h1 into the other buffer
        {
            const __half* gB = &g_Bh[(size_t)(t*N_ + b0)*H0_];
            #pragma unroll
            for (int i = 0; i < 2; i++) pair_build_g(bufp[cur ^ 1], Ar1, gB, i, tid);
        }
        __syncthreads();
        if (tid < 16)
            score_out[a0*N_ + b0 + tid] = sigmoidf_(sred[tid] + b3);
        if (tid < H1_ && tid >= 16) ;           // (sred[16..] untouched by m16 epilogue)
        __syncthreads();
        if (tid < 16) sred[tid] = 0.f;
        __syncthreads();

        // ---- m16 GEMM + epilogue for a1 ----
        unsigned nxtu = bufu[cur ^ 1];
        if (warp_m == 0){
            float d[4][4];
            #pragma unroll
            for (int j=0;j<4;j++)
                #pragma unroll
                for (int v=0;v<4;v++) d[j][v]=0.f;
            #pragma unroll 4
            for (int ks = 0; ks < 16; ks++){
                unsigned afr[4], bfr[2][4];
                ldsm_x4(afr, nxtu + ((a_trow)*ROWH + a_tcol8)*2 + ks*32);
                #pragma unroll
                for (int nb = 0; nb < 2; nb++) ldsm_x4(bfr[nb], bA[nb] + ks*32);
                #pragma unroll
                for (int nb = 0; nb < 2; nb++){
                    mma16816(d[nb*2+0], afr, &bfr[nb][0]);
                    mma16816(d[nb*2+1], afr, &bfr[nb][2]);
                }
            }
            #pragma unroll
            for (int h = 0; h < 2; h++){
                float part = 0.f;
                #pragma unroll
                for (int n8 = 0; n8 < 4; n8++){
                    #pragma unroll
                    for (int c = 0; c < 2; c++){
                        int j = warp_n*32 + n8*8 + (lane & 3)*2 + c;
                        part += fmaxf(d[n8][h*2 + c] + b2s[j], 0.f) * w3s[j];
                    }
                }
                part += __shfl_xor_sync(0xffffffff, part, 1);
                part += __shfl_xor_sync(0xffffffff, part, 2);
                if ((lane & 3) == 0)
                    atomicAdd(&sred[(lane >> 2) + h*8], part);
            }
        }
        __syncthreads();
        if (tid < 16)
            score_out[a1*N_ + b0 + tid] = sigmoidf_(sred[tid] + b3);
    }
}

// ---------------------------------------------------------------------------
// Kernel 2b: learned_adj -> fp16
// ---------------------------------------------------------------------------
__global__ void k_ladj(const float* __restrict__ adj, const float* __restrict__ score)
{
    int idx = blockIdx.x*256 + threadIdx.x;
    if (idx >= T_*N_*N_) return;
    int t = idx / (N_*N_);
    int r = idx % (N_*N_);
    int n = r / N_, m = r % N_;
    float v = score[idx];
    if (n < S_ && m < S_)
        v = (adj[(t*S_ + n)*S_ + m] > 0.f) ? 1.f : -v;
    g_ladjH[idx] = __float2half_rn(v);
}

// ---------------------------------------------------------------------------
// Kernel 3: support (hi/lo split, 3 passes), 64x64 tiles
// ---------------------------------------------------------------------------
__global__ void __launch_bounds__(256)
k_support(const float* __restrict__ nf, const float* __restrict__ Wg)
{
    __shared__ __align__(16) __half Ah[64*72];
    __shared__ __align__(16) __half Al[64*72];
    __shared__ __align__(16) __half Bh[64*72];
    __shared__ __align__(16) __half Bl[64*72];
    int tid = threadIdx.x, lane = tid & 31, wid = tid >> 5;
    int warp_m = wid >> 1, warp_n = wid & 1;
    int o0 = blockIdx.x*64, m0 = blockIdx.y*64;
    unsigned Ahu = smem_u32(Ah), Alu = smem_u32(Al);
    unsigned Bhu = smem_u32(Bh), Blu = smem_u32(Bl);
    float d[4][4] = {};

    for (int k0 = 0; k0 < GD_; k0 += 64){
        #pragma unroll
        for (int i = 0; i < 4; i++){
            int idx = i*256 + tid;
            int row = idx >> 4, c4 = idx & 15;
            int m = m0 + row, f = k0 + c4*4;
            float4 v = make_float4(0.f,0.f,0.f,0.f);
            if (m < TNROWS){
                int tt = m / N_, n = m % N_;
                int node = (f < D_) ? n : (S_ + (f >> 7) - 1);
                v = *(const float4*)&nf[(tt*N_ + node)*D_ + (f & 127)];
            }
            __half h0,l0,h1,l1,h2,l2,h3,l3;
            split2(v.x,h0,l0); split2(v.y,h1,l1); split2(v.z,h2,l2); split2(v.w,h3,l3);
            *(__half2*)&Ah[row*72 + c4*4]     = __halves2half2(h0,h1);
            *(__half2*)&Ah[row*72 + c4*4 + 2] = __halves2half2(h2,h3);
            *(__half2*)&Al[row*72 + c4*4]     = __halves2half2(l0,l1);
            *(__half2*)&Al[row*72 + c4*4 + 2] = __halves2half2(l2,l3);
        }
        #pragma unroll
        for (int i = 0; i < 4; i++){
            int idx = i*256 + tid;
            int row = idx >> 4, c4 = idx & 15;
            float4 v = *(const float4*)&Wg[(k0 + row)*GD_ + o0 + c4*4];
            __half h0,l0,h1,l1,h2,l2,h3,l3;
            split2(v.x,h0,l0); split2(v.y,h1,l1); split2(v.z,h2,l2); split2(v.w,h3,l3);
            *(__half2*)&Bh[row*72 + c4*4]     = __halves2half2(h0,h1);
            *(__half2*)&Bh[row*72 + c4*4 + 2] = __halves2half2(h2,h3);
            *(__half2*)&Bl[row*72 + c4*4]     = __halves2half2(l0,l1);
            *(__half2*)&Bl[row*72 + c4*4 + 2] = __halves2half2(l2,l3);
        }
        __syncthreads();
        mma_m16n32_t(d, Ahu, Bhu, lane, warp_m, warp_n, 72, 72);
        mma_m16n32_t(d, Ahu, Blu, lane, warp_m, warp_n, 72, 72);
        mma_m16n32_t(d, Alu, Bhu, lane, warp_m, warp_n, 72, 72);
        __syncthreads();
    }
    #pragma unroll
    for (int n8 = 0; n8 < 4; n8++)
        #pragma unroll
        for (int v = 0; v < 4; v++){
            int row = m0 + warp_m*16 + (lane >> 2) + (v >> 1)*8;
            int col = o0 + warp_n*32 + n8*8 + (lane & 3)*2 + (v & 1);
            if (row < TNROWS){
                __half h, l;
                split2(d[n8][v], h, l);
                g_supH[row*GD_ + col] = h;
                g_supL[row*GD_ + col] = l;
            }
        }
}

// ---------------------------------------------------------------------------
// Kernel 4: wl = relu(ladj·sup + biasG), 64x64 tiles, B hi+lo (2 passes)
// ---------------------------------------------------------------------------
__global__ void __launch_bounds__(256)
k_wl(const float* __restrict__ biasG)
{
    __shared__ __align__(16) __half As[64*72];
    __shared__ __align__(16) __half Bh[64*72];
    __shared__ __align__(16) __half Bl[64*72];
    int tid = threadIdx.x, lane = tid & 31, wid = tid >> 5;
    int warp_m = wid >> 1, warp_n = wid & 1;
    int o0 = blockIdx.x*64, m0 = blockIdx.y*64, t = blockIdx.z;
    unsigned Asu = smem_u32(As), Bhu = smem_u32(Bh), Blu = smem_u32(Bl);
    float d[4][4] = {};

    for (int k0 = 0; k0 < N_; k0 += 64){
        #pragma unroll
        for (int i = 0; i < 2; i++){
            int idx = i*256 + tid;
            int row = idx >> 3, c8 = idx & 7;
            int n = m0 + row, k = k0 + c8*8;
            uint4 v = make_uint4(0u,0u,0u,0u);
            if (n < N_ && k < N_)
                v = *(const uint4*)&g_ladjH[(t*N_ + n)*N_ + k];
            *(uint4*)&As[row*72 + c8*8] = v;
        }
        #pragma unroll
        for (int i = 0; i < 2; i++){
            int idx = i*256 + tid;
            int row = idx >> 3, c8 = idx & 7;
            int k = k0 + row;
            uint4 vh = make_uint4(0u,0u,0u,0u);
            uint4 vl = make_uint4(0u,0u,0u,0u);
            if (k < N_){
                vh = *(const uint4*)&g_supH[(t*N_ + k)*GD_ + o0 + c8*8];
                vl = *(const uint4*)&g_supL[(t*N_ + k)*GD_ + o0 + c8*8];
            }
            *(uint4*)&Bh[row*72 + c8*8] = vh;
            *(uint4*)&Bl[row*72 + c8*8] = vl;
        }
        __syncthreads();
        mma_m16n32_t(d, Asu, Bhu, lane, warp_m, warp_n, 72, 72);
        mma_m16n32_t(d, Asu, Blu, lane, warp_m, warp_n, 72, 72);
        __syncthreads();
    }
    #pragma unroll
    for (int n8 = 0; n8 < 4; n8++)
        #pragma unroll
        for (int v = 0; v < 4; v++){
            int n = m0 + warp_m*16 + (lane >> 2) + (v >> 1)*8;
            int o = o0 + warp_n*32 + n8*8 + (lane & 3)*2 + (v & 1);
            if (n < N_)
                g_wl[(t*N_ + n)*GD_ + o] = fmaxf(d[n8][v] + biasG[o], 0.f);
        }
}

// ---------------------------------------------------------------------------
// Kernel 5: wl mean over t -> out[0 .. 307200)
// ---------------------------------------------------------------------------
__global__ void k_mean(float* __restrict__ out)
{
    int i = blockIdx.x*blockDim.x + threadIdx.x;
    if (i < N_*GD_){
        float s = g_wl[i] + g_wl[i + N_*GD_] + g_wl[i + 2*N_*GD_] + g_wl[i + 3*N_*GD_];
        out[i] = 0.25f * s;
    }
}

// ---------------------------------------------------------------------------
// Kernel 6: h2a = relu(wl·W1^T + b1), hi/lo split MMA (3 passes), 64x64 tiles
// ---------------------------------------------------------------------------
__global__ void __launch_bounds__(256)
k_fc2a(const float* __restrict__ W, const float* __restrict__ bias)
{
    __shared__ __align__(16) __half Ah[64*72];
    __shared__ __align__(16) __half Al[64*72];
    __shared__ __align__(16) __half Bh[64*72];
    __shared__ __align__(16) __half Bl[64*72];
    int tid = threadIdx.x, lane = tid & 31, wid = tid >> 5;
    int warp_m = wid >> 1, warp_n = wid & 1;
    int o0 = blockIdx.x*64, m0 = blockIdx.y*64;
    unsigned Ahu = smem_u32(Ah), Alu = smem_u32(Al);
    unsigned Bhu = smem_u32(Bh), Blu = smem_u32(Bl);
    float d[4][4] = {};

    for (int k0 = 0; k0 < GD_; k0 += 64){
        #pragma unroll
        for (int i = 0; i < 4; i++){
            int idx = i*256 + tid;
            int row = idx >> 4, c4 = idx & 15;
            int m = m0 + row;
            float4 v = make_float4(0.f,0.f,0.f,0.f);
            if (m < TNROWS) v = *(const float4*)&g_wl[m*GD_ + k0 + c4*4];
            __half h0,l0,h1,l1,h2,l2,h3,l3;
            split2(v.x,h0,l0); split2(v.y,h1,l1); split2(v.z,h2,l2); split2(v.w,h3,l3);
            *(__half2*)&Ah[row*72 + c4*4]     = __halves2half2(h0,h1);
            *(__half2*)&Ah[row*72 + c4*4 + 2] = __halves2half2(h2,h3);
            *(__half2*)&Al[row*72 + c4*4]     = __halves2half2(l0,l1);
            *(__half2*)&Al[row*72 + c4*4 + 2] = __halves2half2(l2,l3);
        }
        #pragma unroll
        for (int i = 0; i < 4; i++){
            int idx = i*256 + tid;
            int row = idx >> 4, c4 = idx & 15;      // row = j (output neuron)
            float4 v = *(const float4*)&W[(o0 + row)*GD_ + k0 + c4*4];
            __half h0,l0,h1,l1,h2,l2,h3,l3;
            split2(v.x,h0,l0); split2(v.y,h1,l1); split2(v.z,h2,l2); split2(v.w,h3,l3);
            *(__half2*)&Bh[row*72 + c4*4]     = __halves2half2(h0,h1);
            *(__half2*)&Bh[row*72 + c4*4 + 2] = __halves2half2(h2,h3);
            *(__half2*)&Bl[row*72 + c4*4]     = __halves2half2(l0,l1);
            *(__half2*)&Bl[row*72 + c4*4 + 2] = __halves2half2(l2,l3);
        }
        __syncthreads();
        mma_m16n32_n(d, Ahu, Bhu, lane, warp_m, warp_n, 72, 72);
        mma_m16n32_n(d, Ahu, Blu, lane, warp_m, warp_n, 72, 72);
        mma_m16n32_n(d, Alu, Bhu, lane, warp_m, warp_n, 72, 72);
        __syncthreads();
    }
    #pragma unroll
    for (int n8 = 0; n8 < 4; n8++)
        #pragma unroll
        for (int v = 0; v < 4; v++){
            int row = m0 + warp_m*16 + (lane >> 2) + (v >> 1)*8;
            int col = o0 + warp_n*32 + n8*8 + (lane & 3)*2 + (v & 1);
            if (row < TNROWS)
                g_h2a[row*H1_ + col] = fmaxf(d[n8][v] + bias[col], 0.f);
        }
}

// ---------------------------------------------------------------------------
// Kernel 7: h2b = relu(h2a·W2^T + b)  fp32 SIMT  M=1600,K=128,O=128
// ---------------------------------------------------------------------------
__global__ void k_fc2b(const float* __restrict__ W, const float* __restrict__ bias)
{
    __shared__ float As[16][64];
    __shared__ float Bs[16][64];
    int tid = threadIdx.x;
    int m0 = blockIdx.y*64, o0 = blockIdx.x*64;
    int tx = tid & 15, ty = tid >> 4;
    float acc[4][4] = {};
    for (int k0 = 0; k0 < H1_; k0 += 16){
        #pragma unroll
        for (int i = 0; i < 4; i++){
            int e = i*256 + tid;
            int r = e >> 4, kk = e & 15;
            As[kk][r] = g_h2a[(m0 + r)*H1_ + k0 + kk];
        }
        {
            int o  = tid >> 2;
            int kq = (tid & 3)*4;
            float4 w = *(const float4*)&W[(o0 + o)*H1_ + k0 + kq];
            Bs[kq+0][o] = w.x; Bs[kq+1][o] = w.y; Bs[kq+2][o] = w.z; Bs[kq+3][o] = w.w;
        }
        __syncthreads();
        #pragma unroll
        for (int kk = 0; kk < 16; kk++){
            float ra[4], rb[4];
            #pragma unroll
            for (int i = 0; i < 4; i++) ra[i] = As[kk][ty*4 + i];
            #pragma unroll
            for (int jj = 0; jj < 4; jj++) rb[jj] = Bs[kk][tx*4 + jj];
            #pragma unroll
            for (int i = 0; i < 4; i++)
                #pragma unroll
                for (int jj = 0; jj < 4; jj++)
                    acc[i][jj] += ra[i]*rb[jj];
        }
        __syncthreads();
    }
    #pragma unroll
    for (int i = 0; i < 4; i++)
        #pragma unroll
        for (int jj = 0; jj < 4; jj++){
            int o = o0 + tx*4 + jj;
            g_h2b[(m0 + ty*4 + i)*H1_ + o] = fmaxf(acc[i][jj] + bias[o], 0.f);
        }
}

// ---------------------------------------------------------------------------
// Kernel 8: query[t,c,n] = sigmoid( h2b[t,n,:]·w3[c,:] + b3[c] )
// ---------------------------------------------------------------------------
__global__ void k_query(const float* __restrict__ w3, const float* __restrict__ b3,
                        float* __restrict__ out)
{
    int idx = blockIdx.x*blockDim.x + threadIdx.x;
    if (idx >= TNROWS*5) return;
    int row = idx / 5, c = idx % 5;
    const float* h = g_h2b + row*H1_;
    const float* w = w3 + c*H1_;
    float s = 0.f;
    #pragma unroll 8
    for (int k = 0; k < H1_; k++) s += h[k]*w[k];
    int t = row / N_, n = row % N_;
    out[OUT_QS + t*5*N_ + c*N_ + n] = sigmoidf_(s + b3[c]);
}

// ---------------------------------------------------------------------------
extern "C" void kernel_launch(void* const* d_in, const int* in_sizes, int n_in,
                              void* d_out, int out_size)
{
    const float* nf       = (const float*)d_in[0];
    const float* adj      = (const float*)d_in[1];
    const float* fc1_w1   = (const float*)d_in[2];
    const float* fc1_b1   = (const float*)d_in[3];
    const float* fc1_w2   = (const float*)d_in[4];
    const float* fc1_b2   = (const float*)d_in[5];
    const float* fc1_w3   = (const float*)d_in[6];
    const float* fc1_b3   = (const float*)d_in[7];
    const float* weight_G = (const float*)d_in[8];
    const float* bias_G   = (const float*)d_in[9];
    const float* fc2_w1   = (const float*)d_in[10];
    const float* fc2_b1   = (const float*)d_in[11];
    const float* fc2_w2   = (const float*)d_in[12];
    const float* fc2_b2   = (const float*)d_in[13];
    const float* fc2_w3   = (const float*)d_in[14];
    const float* fc2_b3   = (const float*)d_in[15];

    float* out       = (float*)d_out;
    float* score_out = out + OUT_SCORE;

    size_t smem_pair = (size_t)(3*128*ROWH + 2*H0_)*sizeof(__half)
                     + (size_t)(3*H1_)*sizeof(float);
    cudaFuncSetAttribute(k_pair, cudaFuncAttributeMaxDynamicSharedMemorySize, (int)smem_pair);

    k_pre<<<dim3(8, 25), 256>>>(nf, fc1_w1, fc1_b1);
    k_w2h<<<(H1_*H0_ + 255)/256, 256>>>(fc1_w2);
    k_pair<<<TNROWS/2, 256, smem_pair>>>(fc1_b2, fc1_w3, fc1_b3, score_out);
    k_ladj<<<(T_*N_*N_ + 255)/256, 256>>>(adj, score_out);
    k_support<<<dim3(GD_/64, (TNROWS + 63)/64), 256>>>(nf, weight_G);
    k_wl<<<dim3(GD_/64, (N_ + 63)/64, T_), 256>>>(bias_G);
    k_mean<<<(N_*GD_ + 255)/256, 256>>>(out);
    k_fc2a<<<dim3(H1_/64, (TNROWS + 63)/64), 256>>>(fc2_w1, fc2_b1);
    k_fc2b<<<dim3(H1_/64, TNROWS/64), 256>>>(fc2_w2, fc2_b2);
    k_query<<<(TNROWS*5 + 127)/128, 128>>>(fc2_w3, fc2_b3, out);
}

// round 15
// speedup vs baseline: 1.1600x; 1.1600x over previous
#include <cuda_runtime.h>
#include <cuda_fp16.h>
#include <math.h>

#define T_  4
#define N_  400
#define S_  395
#define D_  128
#define H0_ 256
#define H1_ 128
#define GD_ 768
#define TNROWS (T_*N_)           // 1600

// output layout: [wl_mean (400*768)] [learned_score (4*400*400)] [query^T (4*5*400)]
#define OUT_SCORE (N_*GD_)               // 307200
#define OUT_QS    (OUT_SCORE + T_*N_*N_) // 947200

#define ROWH 264                 // padded half-row stride for k_pair ldmatrix tiles

__device__ __half g_ABh[TNROWS*H0_];     // fp16(A + b1)
__device__ __half g_Bh [TNROWS*H0_];     // fp16(B)
__device__ __half g_W2h[H1_*H0_];        // fp16(fc1_w2)
__device__ __half g_ladjH[T_*N_*N_];     // fp16(learned_adj)
__device__ __half g_supH[TNROWS*GD_];
__device__ __half g_supL[TNROWS*GD_];
__device__ float  g_wl[TNROWS*GD_];
__device__ float  g_h2a[TNROWS*H1_];

__device__ __forceinline__ float sigmoidf_(float x){ return 1.0f/(1.0f + __expf(-x)); }

__device__ __forceinline__ unsigned smem_u32(const void* p){
    unsigned a;
    asm("{ .reg .u64 t; cvta.to.shared.u64 t, %1; cvt.u32.u64 %0, t; }" : "=r"(a) : "l"(p));
    return a;
}
__device__ __forceinline__ void ldsm_x4(unsigned* r, unsigned addr){
    asm volatile("ldmatrix.sync.aligned.m8n8.x4.shared.b16 {%0,%1,%2,%3}, [%4];"
        : "=r"(r[0]), "=r"(r[1]), "=r"(r[2]), "=r"(r[3]) : "r"(addr));
}
__device__ __forceinline__ void ldsm_x4_t(unsigned* r, unsigned addr){
    asm volatile("ldmatrix.sync.aligned.m8n8.x4.trans.shared.b16 {%0,%1,%2,%3}, [%4];"
        : "=r"(r[0]), "=r"(r[1]), "=r"(r[2]), "=r"(r[3]) : "r"(addr));
}
__device__ __forceinline__ void mma16816(float* d, const unsigned* a, const unsigned* b){
    asm volatile("mma.sync.aligned.m16n8k16.row.col.f32.f16.f16.f32 "
        "{%0,%1,%2,%3},{%4,%5,%6,%7},{%8,%9},{%0,%1,%2,%3};"
        : "+f"(d[0]), "+f"(d[1]), "+f"(d[2]), "+f"(d[3])
        : "r"(a[0]), "r"(a[1]), "r"(a[2]), "r"(a[3]), "r"(b[0]), "r"(b[1]));
}
__device__ __forceinline__ void split2(float x, __half& h, __half& l){
    h = __float2half_rn(x);
    l = __float2half_rn(x - __half2float(h));
}
__device__ __forceinline__ void mma_m16n32_t(float d[4][4], unsigned Asu, unsigned Bsu,
                                             int lane, int warp_m, int warp_n, int PA, int PB)
{
    int ar = lane & 15, ac = (lane >> 4) * 8;
    int bk = ((lane >> 3) & 1) * 8 + (lane & 7);
    int bj = ((lane >> 4) & 1) * 8;
    #pragma unroll
    for (int ks = 0; ks < 4; ks++){
        unsigned a[4], b[2][4];
        ldsm_x4(a, Asu + (unsigned)(((warp_m*16 + ar)*PA + ks*16 + ac)*2));
        #pragma unroll
        for (int nb = 0; nb < 2; nb++)
            ldsm_x4_t(b[nb], Bsu + (unsigned)(((ks*16 + bk)*PB + warp_n*32 + nb*16 + bj)*2));
        #pragma unroll
        for (int nb = 0; nb < 2; nb++){
            mma16816(d[nb*2+0], a, &b[nb][0]);
            mma16816(d[nb*2+1], a, &b[nb][2]);
        }
    }
}
__device__ __forceinline__ void mma_m16n32_n(float d[4][4], unsigned Asu, unsigned Bsu,
                                             int lane, int warp_m, int warp_n, int PA, int PB)
{
    int ar = lane & 15, ac = (lane >> 4) * 8;
    int bg = lane >> 3;
    int bj = ((bg >= 2) ? 8 : 0) + (lane & 7);
    int bk2 = (bg & 1) * 8;
    #pragma unroll
    for (int ks = 0; ks < 4; ks++){
        unsigned a[4], b[2][4];
        ldsm_x4(a, Asu + (unsigned)(((warp_m*16 + ar)*PA + ks*16 + ac)*2));
        #pragma unroll
        for (int nb = 0; nb < 2; nb++)
            ldsm_x4(b[nb], Bsu + (unsigned)(((warp_n*32 + nb*16 + bj)*PB + ks*16 + bk2)*2));
        #pragma unroll
        for (int nb = 0; nb < 2; nb++){
            mma16816(d[nb*2+0], a, &b[nb][0]);
            mma16816(d[nb*2+1], a, &b[nb][2]);
        }
    }
}

// ---------------------------------------------------------------------------
// Kernel 1: A/B precompute -> fp16 g_ABh (A+b1), g_Bh; + W2->fp16 fold
// ---------------------------------------------------------------------------
__global__ void k_pre(const float* __restrict__ nf, const float* __restrict__ w1,
                      const float* __restrict__ b1, const float* __restrict__ w2)
{
    __shared__ float As[16][64];
    __shared__ float Bs[16][64];
    int tid = threadIdx.x;
    int m0 = blockIdx.y*64, h0 = blockIdx.x*64;
    int tx = tid & 15, ty = tid >> 4;

    // folded: W2 -> fp16 (200 blocks x 256 threads cover 32768 elems)
    {
        int i = (blockIdx.y*8 + blockIdx.x)*256 + tid;
        if (i < H1_*H0_) g_W2h[i] = __float2half_rn(w2[i]);
    }

    float acc[4][4] = {};
    for (int k0 = 0; k0 < D_; k0 += 16){
        #pragma unroll
        for (int i = 0; i < 4; i++){
            int e = i*256 + tid;
            int r = e >> 4, kk = e & 15;
            As[kk][r] = nf[(m0 + r)*D_ + k0 + kk];
        }
        {
            int o  = tid >> 2;
            int kq = (tid & 3)*4;
            int hp = h0 + o;
            const float* src = w1 + (hp & 255)*(2*D_) + (hp >> 8)*D_ + k0 + kq;
            float4 w = *(const float4*)src;
            Bs[kq+0][o] = w.x; Bs[kq+1][o] = w.y; Bs[kq+2][o] = w.z; Bs[kq+3][o] = w.w;
        }
        __syncthreads();
        #pragma unroll
        for (int kk = 0; kk < 16; kk++){
            float ra[4], rb[4];
            #pragma unroll
            for (int i = 0; i < 4; i++) ra[i] = As[kk][ty*4 + i];
            #pragma unroll
            for (int jj = 0; jj < 4; jj++) rb[jj] = Bs[kk][tx*4 + jj];
            #pragma unroll
            for (int i = 0; i < 4; i++)
                #pragma unroll
                for (int jj = 0; jj < 4; jj++)
                    acc[i][jj] += ra[i]*rb[jj];
        }
        __syncthreads();
    }
    #pragma unroll
    for (int i = 0; i < 4; i++)
        #pragma unroll
        for (int jj = 0; jj < 4; jj++){
            int hp = h0 + tx*4 + jj;
            int row = m0 + ty*4 + i;
            float v = acc[i][jj];
            if (hp < H0_) g_ABh[row*H0_ + hp]         = __float2half_rn(v + b1[hp]);
            else          g_Bh [row*H0_ + (hp - 256)] = __float2half_rn(v);
        }
}

// ---------------------------------------------------------------------------
// Kernel 2: pairwise MLP (R12 structure) + fused learned_adj fp16 write.
// ---------------------------------------------------------------------------
__global__ void __launch_bounds__(256, 1)
k_pair(const float* __restrict__ b2v, const float* __restrict__ w3,
       const float* __restrict__ b3v, const float* __restrict__ adj,
       float* __restrict__ score_out)
{
    extern __shared__ char smraw[];
    __half* h1s = (__half*)smraw;                 // 128*ROWH
    __half* W2s = h1s + 128*ROWH;                 // 128*ROWH
    __half* rBs = W2s + 128*ROWH;                 // 128*ROWH (raw B tile)
    __half* Ar0 = rBs + 128*ROWH;                 // 256
    __half* Ar1 = Ar0 + H0_;                      // 256
    float*  sred = (float*)(Ar1 + H0_);           // 128
    float*  b2s  = sred + H1_;                    // 128
    float*  w3s  = b2s + H1_;                     // 128

    int a0 = blockIdx.x*2, a1 = a0 + 1;
    int t  = a0 / N_;
    int a0l = a0 - t*N_;                          // local a indices (never straddle t)
    int a1l = a0l + 1;
    int tid = threadIdx.x, lane = tid & 31, wid = tid >> 5;
    int warp_n = wid & 3, warp_m = wid >> 2;

    // stage W2 (fp16 copy), A rows, biases
    #pragma unroll
    for (int i = 0; i < 16; i++){
        int idx = i*256 + tid;
        int row = idx >> 5, c8 = idx & 31;
        *(uint4*)&W2s[row*ROWH + c8*8] = *(const uint4*)&g_W2h[row*H0_ + c8*8];
    }
    Ar0[tid] = g_ABh[a0*H0_ + tid];
    Ar1[tid] = g_ABh[a1*H0_ + tid];
    if (tid < H1_){ b2s[tid] = b2v[tid]; w3s[tid] = w3[tid]; }
    float b3 = b3v[0];

    unsigned h1u = smem_u32(h1s);
    unsigned w2u = smem_u32(W2s);

    int a_trow  = lane & 15;
    int a_tcol8 = (lane >> 4) * 8;
    int b_g     = lane >> 3;
    int b_joff  = ((b_g >= 2) ? 8 : 0) + (lane & 7);
    int b_koff  = (b_g & 1) * 8;

    unsigned aA[4], bA[2];
    #pragma unroll
    for (int mt = 0; mt < 4; mt++)
        aA[mt] = h1u + ((warp_m*64 + mt*16 + a_trow)*ROWH + a_tcol8)*2;
    #pragma unroll
    for (int nb = 0; nb < 2; nb++)
        bA[nb] = w2u + ((warp_n*32 + nb*16 + b_joff)*ROWH + b_koff)*2;

    const __half2 z2 = __float2half2_rn(0.f);

    // ======== full tiles b0 = 0, 128, 256 ========
    for (int b0 = 0; b0 < 384; b0 += 128){
        __syncthreads();
        // stage raw B + h1 for a0
        #pragma unroll
        for (int i = 0; i < 16; i++){
            int idx = i*256 + tid;
            int row = idx >> 5, c8 = idx & 31;
            uint4 v = *(const uint4*)&g_Bh[((size_t)(t*N_ + b0 + row))*H0_ + c8*8];
            *(uint4*)&rBs[row*ROWH + c8*8] = v;
            const __half2* vp = (const __half2*)&v;
            uint4 o; __half2* op = (__half2*)&o;
            #pragma unroll
            for (int q = 0; q < 4; q++)
                op[q] = __hmax2(__hadd2(vp[q], *(const __half2*)&Ar0[c8*8 + q*2]), z2);
            *(uint4*)&h1s[row*ROWH + c8*8] = o;
        }
        if (tid < H1_) sred[tid] = 0.f;
        __syncthreads();

        // ---- GEMM + epilogue for a0 ----
        {
            float d[4][4][4];
            #pragma unroll
            for (int i=0;i<4;i++)
                #pragma unroll
                for (int j=0;j<4;j++)
                    #pragma unroll
                    for (int v=0;v<4;v++) d[i][j][v]=0.f;
            #pragma unroll 4
            for (int ks = 0; ks < 16; ks++){
                unsigned afr[4][4], bfr[2][4];
                #pragma unroll
                for (int mt = 0; mt < 4; mt++) ldsm_x4(afr[mt], aA[mt] + ks*32);
                #pragma unroll
                for (int nb = 0; nb < 2; nb++) ldsm_x4(bfr[nb], bA[nb] + ks*32);
                #pragma unroll
                for (int mt = 0; mt < 4; mt++)
                    #pragma unroll
                    for (int nb = 0; nb < 2; nb++){
                        mma16816(d[mt][nb*2+0], afr[mt], &bfr[nb][0]);
                        mma16816(d[mt][nb*2+1], afr[mt], &bfr[nb][2]);
                    }
            }
            #pragma unroll
            for (int mt = 0; mt < 4; mt++){
                #pragma unroll
                for (int h = 0; h < 2; h++){
                    float part = 0.f;
                    #pragma unroll
                    for (int n8 = 0; n8 < 4; n8++){
                        #pragma unroll
                        for (int c = 0; c < 2; c++){
                            int j = warp_n*32 + n8*8 + (lane & 3)*2 + c;
                            part += fmaxf(d[mt][n8][h*2 + c] + b2s[j], 0.f) * w3s[j];
                        }
                    }
                    part += __shfl_xor_sync(0xffffffff, part, 1);
                    part += __shfl_xor_sync(0xffffffff, part, 2);
                    if ((lane & 3) == 0)
                        atomicAdd(&sred[warp_m*64 + mt*16 + (lane >> 2) + h*8], part);
                }
            }
        }
        __syncthreads();
        if (tid < H1_){
            int b = b0 + tid;
            float sc = sigmoidf_(sred[tid] + b3);
            score_out[a0*N_ + b] = sc;
            float lv = sc;
            if (a0l < S_ && b < S_)
                lv = (adj[(t*S_ + a0l)*S_ + b] > 0.f) ? 1.f : -sc;
            g_ladjH[a0*N_ + b] = __float2half_rn(lv);
            sred[tid] = 0.f;
        }
        // stage h1 for a1 from rBs (smem only)
        #pragma unroll
        for (int i = 0; i < 16; i++){
            int idx = i*256 + tid;
            int row = idx >> 5, c8 = idx & 31;
            uint4 v = *(const uint4*)&rBs[row*ROWH + c8*8];
            const __half2* vp = (const __half2*)&v;
            uint4 o; __half2* op = (__half2*)&o;
            #pragma unroll
            for (int q = 0; q < 4; q++)
                op[q] = __hmax2(__hadd2(vp[q], *(const __half2*)&Ar1[c8*8 + q*2]), z2);
            *(uint4*)&h1s[row*ROWH + c8*8] = o;
        }
        __syncthreads();

        // ---- GEMM + epilogue for a1 ----
        {
            float d[4][4][4];
            #pragma unroll
            for (int i=0;i<4;i++)
                #pragma unroll
                for (int j=0;j<4;j++)
                    #pragma unroll
                    for (int v=0;v<4;v++) d[i][j][v]=0.f;
            #pragma unroll 4
            for (int ks = 0; ks < 16; ks++){
                unsigned afr[4][4], bfr[2][4];
                #pragma unroll
                for (int mt = 0; mt < 4; mt++) ldsm_x4(afr[mt], aA[mt] + ks*32);
                #pragma unroll
                for (int nb = 0; nb < 2; nb++) ldsm_x4(bfr[nb], bA[nb] + ks*32);
                #pragma unroll
                for (int mt = 0; mt < 4; mt++)
                    #pragma unroll
                    for (int nb = 0; nb < 2; nb++){
                        mma16816(d[mt][nb*2+0], afr[mt], &bfr[nb][0]);
                        mma16816(d[mt][nb*2+1], afr[mt], &bfr[nb][2]);
                    }
            }
            #pragma unroll
            for (int mt = 0; mt < 4; mt++){
                #pragma unroll
                for (int h = 0; h < 2; h++){
                    float part = 0.f;
                    #pragma unroll
                    for (int n8 = 0; n8 < 4; n8++){
                        #pragma unroll
                        for (int c = 0; c < 2; c++){
                            int j = warp_n*32 + n8*8 + (lane & 3)*2 + c;
                            part += fmaxf(d[mt][n8][h*2 + c] + b2s[j], 0.f) * w3s[j];
                        }
                    }
                    part += __shfl_xor_sync(0xffffffff, part, 1);
                    part += __shfl_xor_sync(0xffffffff, part, 2);
                    if ((lane & 3) == 0)
                        atomicAdd(&sred[warp_m*64 + mt*16 + (lane >> 2) + h*8], part);
                }
            }
        }
        __syncthreads();
        if (tid < H1_){
            int b = b0 + tid;
            float sc = sigmoidf_(sred[tid] + b3);
            score_out[a1*N_ + b] = sc;
            float lv = sc;
            if (a1l < S_ && b < S_)
                lv = (adj[(t*S_ + a1l)*S_ + b] > 0.f) ? 1.f : -sc;
            g_ladjH[a1*N_ + b] = __float2half_rn(lv);
        }
    }

    // ======== tail tile b0 = 384, 16 valid rows (m16 GEMM) ========
    {
        const int b0 = 384;
        __syncthreads();
        #pragma unroll
        for (int i = 0; i < 2; i++){
            int idx = i*256 + tid;
            int row = idx >> 5, c8 = idx & 31;
            uint4 v = *(const uint4*)&g_Bh[((size_t)(t*N_ + b0 + row))*H0_ + c8*8];
            *(uint4*)&rBs[row*ROWH + c8*8] = v;
            const __half2* vp = (const __half2*)&v;
            uint4 o; __half2* op = (__half2*)&o;
            #pragma unroll
            for (int q = 0; q < 4; q++)
                op[q] = __hmax2(__hadd2(vp[q], *(const __half2*)&Ar0[c8*8 + q*2]), z2);
            *(uint4*)&h1s[row*ROWH + c8*8] = o;
        }
        if (tid < H1_) sred[tid] = 0.f;
        __syncthreads();

        // ---- m16 GEMM + epilogue for a0 ----
        if (warp_m == 0){
            float d[4][4];
            #pragma unroll
            for (int j=0;j<4;j++)
                #pragma unroll
                for (int v=0;v<4;v++) d[j][v]=0.f;
            #pragma unroll 4
            for (int ks = 0; ks < 16; ks++){
                unsigned afr[4], bfr[2][4];
                ldsm_x4(afr, h1u + ((a_trow)*ROWH + a_tcol8)*2 + ks*32);
                #pragma unroll
                for (int nb = 0; nb < 2; nb++) ldsm_x4(bfr[nb], bA[nb] + ks*32);
                #pragma unroll
                for (int nb = 0; nb < 2; nb++){
                    mma16816(d[nb*2+0], afr, &bfr[nb][0]);
                    mma16816(d[nb*2+1], afr, &bfr[nb][2]);
                }
            }
            #pragma unroll
            for (int h = 0; h < 2; h++){
                float part = 0.f;
                #pragma unroll
                for (int n8 = 0; n8 < 4; n8++){
                    #pragma unroll
                    for (int c = 0; c < 2; c++){
                        int j = warp_n*32 + n8*8 + (lane & 3)*2 + c;
                        part += fmaxf(d[n8][h*2 + c] + b2s[j], 0.f) * w3s[j];
                    }
                }
                part += __shfl_xor_sync(0xffffffff, part, 1);
                part += __shfl_xor_sync(0xffffffff, part, 2);
                if ((lane & 3) == 0)
                    atomicAdd(&sred[(lane >> 2) + h*8], part);
            }
        }
        __syncthreads();
        if (tid < 16){
            int b = b0 + tid;
            float sc = sigmoidf_(sred[tid] + b3);
            score_out[a0*N_ + b] = sc;
            float lv = sc;
            if (a0l < S_ && b < S_)
                lv = (adj[(t*S_ + a0l)*S_ + b] > 0.f) ? 1.f : -sc;
            g_ladjH[a0*N_ + b] = __float2half_rn(lv);
        }
        if (tid < H1_) sred[tid] = 0.f;
        // stage h1(a1) from rBs
        #pragma unroll
        for (int i = 0; i < 2; i++){
            int idx = i*256 + tid;
            int row = idx >> 5, c8 = idx & 31;
            uint4 v = *(const uint4*)&rBs[row*ROWH + c8*8];
            const __half2* vp = (const __half2*)&v;
            uint4 o; __half2* op = (__half2*)&o;
            #pragma unroll
            for (int q = 0; q < 4; q++)
                op[q] = __hmax2(__hadd2(vp[q], *(const __half2*)&Ar1[c8*8 + q*2]), z2);
            *(uint4*)&h1s[row*ROWH + c8*8] = o;
        }
        __syncthreads();

        // ---- m16 GEMM + epilogue for a1 ----
        if (warp_m == 0){
            float d[4][4];
            #pragma unroll
            for (int j=0;j<4;j++)
                #pragma unroll
                for (int v=0;v<4;v++) d[j][v]=0.f;
            #pragma unroll 4
            for (int ks = 0; ks < 16; ks++){
                unsigned afr[4], bfr[2][4];
                ldsm_x4(afr, h1u + ((a_trow)*ROWH + a_tcol8)*2 + ks*32);
                #pragma unroll
                for (int nb = 0; nb < 2; nb++) ldsm_x4(bfr[nb], bA[nb] + ks*32);
                #pragma unroll
                for (int nb = 0; nb < 2; nb++){
                    mma16816(d[nb*2+0], afr, &bfr[nb][0]);
                    mma16816(d[nb*2+1], afr, &bfr[nb][2]);
                }
            }
            #pragma unroll
            for (int h = 0; h < 2; h++){
                float part = 0.f;
                #pragma unroll
                for (int n8 = 0; n8 < 4; n8++){
                    #pragma unroll
                    for (int c = 0; c < 2; c++){
                        int j = warp_n*32 + n8*8 + (lane & 3)*2 + c;
                        part += fmaxf(d[n8][h*2 + c] + b2s[j], 0.f) * w3s[j];
                    }
                }
                part += __shfl_xor_sync(0xffffffff, part, 1);
                part += __shfl_xor_sync(0xffffffff, part, 2);
                if ((lane & 3) == 0)
                    atomicAdd(&sred[(lane >> 2) + h*8], part);
            }
        }
        __syncthreads();
        if (tid < 16){
            int b = b0 + tid;
            float sc = sigmoidf_(sred[tid] + b3);
            score_out[a1*N_ + b] = sc;
            float lv = sc;
            if (a1l < S_ && b < S_)
                lv = (adj[(t*S_ + a1l)*S_ + b] > 0.f) ? 1.f : -sc;
            g_ladjH[a1*N_ + b] = __float2half_rn(lv);
        }
    }
}

// ---------------------------------------------------------------------------
// Kernel 3: support (hi/lo split, 3 passes), 64x64 tiles; + zero wl_mean out
// ---------------------------------------------------------------------------
__global__ void __launch_bounds__(256)
k_support(const float* __restrict__ nf, const float* __restrict__ Wg,
          float* __restrict__ out)
{
    __shared__ __align__(16) __half Ah[64*72];
    __shared__ __align__(16) __half Al[64*72];
    __shared__ __align__(16) __half Bh[64*72];
    __shared__ __align__(16) __half Bl[64*72];
    int tid = threadIdx.x, lane = tid & 31, wid = tid >> 5;
    int warp_m = wid >> 1, warp_n = wid & 1;
    int o0 = blockIdx.x*64, m0 = blockIdx.y*64;

    // folded: zero out[0 .. 307200) (300 blocks x 256 thr x 4 = exact)
    {
        int bid = blockIdx.y*12 + blockIdx.x;
        int base = bid*256 + tid;
        #pragma unroll
        for (int i = 0; i < 4; i++)
            out[base + i*76800] = 0.f;
    }

    unsigned Ahu = smem_u32(Ah), Alu = smem_u32(Al);
    unsigned Bhu = smem_u32(Bh), Blu = smem_u32(Bl);
    float d[4][4] = {};

    for (int k0 = 0; k0 < GD_; k0 += 64){
        #pragma unroll
        for (int i = 0; i < 4; i++){
            int idx = i*256 + tid;
            int row = idx >> 4, c4 = idx & 15;
            int m = m0 + row, f = k0 + c4*4;
            float4 v = make_float4(0.f,0.f,0.f,0.f);
            if (m < TNROWS){
                int tt = m / N_, n = m % N_;
                int node = (f < D_) ? n : (S_ + (f >> 7) - 1);
                v = *(const float4*)&nf[(tt*N_ + node)*D_ + (f & 127)];
            }
            __half h0,l0,h1,l1,h2,l2,h3,l3;
            split2(v.x,h0,l0); split2(v.y,h1,l1); split2(v.z,h2,l2); split2(v.w,h3,l3);
            *(__half2*)&Ah[row*72 + c4*4]     = __halves2half2(h0,h1);
            *(__half2*)&Ah[row*72 + c4*4 + 2] = __halves2half2(h2,h3);
            *(__half2*)&Al[row*72 + c4*4]     = __halves2half2(l0,l1);
            *(__half2*)&Al[row*72 + c4*4 + 2] = __halves2half2(l2,l3);
        }
        #pragma unroll
        for (int i = 0; i < 4; i++){
            int idx = i*256 + tid;
            int row = idx >> 4, c4 = idx & 15;
            float4 v = *(const float4*)&Wg[(k0 + row)*GD_ + o0 + c4*4];
            __half h0,l0,h1,l1,h2,l2,h3,l3;
            split2(v.x,h0,l0); split2(v.y,h1,l1); split2(v.z,h2,l2); split2(v.w,h3,l3);
            *(__half2*)&Bh[row*72 + c4*4]     = __halves2half2(h0,h1);
            *(__half2*)&Bh[row*72 + c4*4 + 2] = __halves2half2(h2,h3);
            *(__half2*)&Bl[row*72 + c4*4]     = __halves2half2(l0,l1);
            *(__half2*)&Bl[row*72 + c4*4 + 2] = __halves2half2(l2,l3);
        }
        __syncthreads();
        mma_m16n32_t(d, Ahu, Bhu, lane, warp_m, warp_n, 72, 72);
        mma_m16n32_t(d, Ahu, Blu, lane, warp_m, warp_n, 72, 72);
        mma_m16n32_t(d, Alu, Bhu, lane, warp_m, warp_n, 72, 72);
        __syncthreads();
    }
    #pragma unroll
    for (int n8 = 0; n8 < 4; n8++)
        #pragma unroll
        for (int v = 0; v < 4; v++){
            int row = m0 + warp_m*16 + (lane >> 2) + (v >> 1)*8;
            int col = o0 + warp_n*32 + n8*8 + (lane & 3)*2 + (v & 1);
            if (row < TNROWS){
                __half h, l;
                split2(d[n8][v], h, l);
                g_supH[row*GD_ + col] = h;
                g_supL[row*GD_ + col] = l;
            }
        }
}

// ---------------------------------------------------------------------------
// Kernel 4: wl = relu(ladj·sup + biasG) + fused mean atomicAdd into out
// ---------------------------------------------------------------------------
__global__ void __launch_bounds__(256)
k_wl(const float* __restrict__ biasG, float* __restrict__ out)
{
    __shared__ __align__(16) __half As[64*72];
    __shared__ __align__(16) __half Bh[64*72];
    __shared__ __align__(16) __half Bl[64*72];
    int tid = threadIdx.x, lane = tid & 31, wid = tid >> 5;
    int warp_m = wid >> 1, warp_n = wid & 1;
    int o0 = blockIdx.x*64, m0 = blockIdx.y*64, t = blockIdx.z;
    unsigned Asu = smem_u32(As), Bhu = smem_u32(Bh), Blu = smem_u32(Bl);
    float d[4][4] = {};

    for (int k0 = 0; k0 < N_; k0 += 64){
        #pragma unroll
        for (int i = 0; i < 2; i++){
            int idx = i*256 + tid;
            int row = idx >> 3, c8 = idx & 7;
            int n = m0 + row, k = k0 + c8*8;
            uint4 v = make_uint4(0u,0u,0u,0u);
            if (n < N_ && k < N_)
                v = *(const uint4*)&g_ladjH[(t*N_ + n)*N_ + k];
            *(uint4*)&As[row*72 + c8*8] = v;
        }
        #pragma unroll
        for (int i = 0; i < 2; i++){
            int idx = i*256 + tid;
            int row = idx >> 3, c8 = idx & 7;
            int k = k0 + row;
            uint4 vh = make_uint4(0u,0u,0u,0u);
            uint4 vl = make_uint4(0u,0u,0u,0u);
            if (k < N_){
                vh = *(const uint4*)&g_supH[(t*N_ + k)*GD_ + o0 + c8*8];
                vl = *(const uint4*)&g_supL[(t*N_ + k)*GD_ + o0 + c8*8];
            }
            *(uint4*)&Bh[row*72 + c8*8] = vh;
            *(uint4*)&Bl[row*72 + c8*8] = vl;
        }
        __syncthreads();
        mma_m16n32_t(d, Asu, Bhu, lane, warp_m, warp_n, 72, 72);
        mma_m16n32_t(d, Asu, Blu, lane, warp_m, warp_n, 72, 72);
        __syncthreads();
    }
    #pragma unroll
    for (int n8 = 0; n8 < 4; n8++)
        #pragma unroll
        for (int v = 0; v < 4; v++){
            int n = m0 + warp_m*16 + (lane >> 2) + (v >> 1)*8;
            int o = o0 + warp_n*32 + n8*8 + (lane & 3)*2 + (v & 1);
            if (n < N_){
                float val = fmaxf(d[n8][v] + biasG[o], 0.f);
                g_wl[(t*N_ + n)*GD_ + o] = val;
                atomicAdd(&out[n*GD_ + o], 0.25f*val);
            }
        }
}

// ---------------------------------------------------------------------------
// Kernel 6: h2a = relu(wl·W1^T + b1), hi/lo split MMA (3 passes), 64x64 tiles
// ---------------------------------------------------------------------------
__global__ void __launch_bounds__(256)
k_fc2a(const float* __restrict__ W, const float* __restrict__ bias)
{
    __shared__ __align__(16) __half Ah[64*72];
    __shared__ __align__(16) __half Al[64*72];
    __shared__ __align__(16) __half Bh[64*72];
    __shared__ __align__(16) __half Bl[64*72];
    int tid = threadIdx.x, lane = tid & 31, wid = tid >> 5;
    int warp_m = wid >> 1, warp_n = wid & 1;
    int o0 = blockIdx.x*64, m0 = blockIdx.y*64;
    unsigned Ahu = smem_u32(Ah), Alu = smem_u32(Al);
    unsigned Bhu = smem_u32(Bh), Blu = smem_u32(Bl);
    float d[4][4] = {};

    for (int k0 = 0; k0 < GD_; k0 += 64){
        #pragma unroll
        for (int i = 0; i < 4; i++){
            int idx = i*256 + tid;
            int row = idx >> 4, c4 = idx & 15;
            int m = m0 + row;
            float4 v = make_float4(0.f,0.f,0.f,0.f);
            if (m < TNROWS) v = *(const float4*)&g_wl[m*GD_ + k0 + c4*4];
            __half h0,l0,h1,l1,h2,l2,h3,l3;
            split2(v.x,h0,l0); split2(v.y,h1,l1); split2(v.z,h2,l2); split2(v.w,h3,l3);
            *(__half2*)&Ah[row*72 + c4*4]     = __halves2half2(h0,h1);
            *(__half2*)&Ah[row*72 + c4*4 + 2] = __halves2half2(h2,h3);
            *(__half2*)&Al[row*72 + c4*4]     = __halves2half2(l0,l1);
            *(__half2*)&Al[row*72 + c4*4 + 2] = __halves2half2(l2,l3);
        }
        #pragma unroll
        for (int i = 0; i < 4; i++){
            int idx = i*256 + tid;
            int row = idx >> 4, c4 = idx & 15;      // row = j (output neuron)
            float4 v = *(const float4*)&W[(o0 + row)*GD_ + k0 + c4*4];
            __half h0,l0,h1,l1,h2,l2,h3,l3;
            split2(v.x,h0,l0); split2(v.y,h1,l1); split2(v.z,h2,l2); split2(v.w,h3,l3);
            *(__half2*)&Bh[row*72 + c4*4]     = __halves2half2(h0,h1);
            *(__half2*)&Bh[row*72 + c4*4 + 2] = __halves2half2(h2,h3);
            *(__half2*)&Bl[row*72 + c4*4]     = __halves2half2(l0,l1);
            *(__half2*)&Bl[row*72 + c4*4 + 2] = __halves2half2(l2,l3);
        }
        __syncthreads();
        mma_m16n32_n(d, Ahu, Bhu, lane, warp_m, warp_n, 72, 72);
        mma_m16n32_n(d, Ahu, Blu, lane, warp_m, warp_n, 72, 72);
        mma_m16n32_n(d, Alu, Bhu, lane, warp_m, warp_n, 72, 72);
        __syncthreads();
    }
    #pragma unroll
    for (int n8 = 0; n8 < 4; n8++)
        #pragma unroll
        for (int v = 0; v < 4; v++){
            int row = m0 + warp_m*16 + (lane >> 2) + (v >> 1)*8;
            int col = o0 + warp_n*32 + n8*8 + (lane & 3)*2 + (v & 1);
            if (row < TNROWS)
                g_h2a[row*H1_ + col] = fmaxf(d[n8][v] + bias[col], 0.f);
        }
}

// ---------------------------------------------------------------------------
// Kernel 7 (fused fc2b + query): per block 64 m-rows x full O=128; query
// computed in-block from smem h2b. (h2bs pad 130 -> 48,128B static smem.)
// ---------------------------------------------------------------------------
__global__ void __launch_bounds__(256)
k_fc2bq(const float* __restrict__ W, const float* __restrict__ bias,
        const float* __restrict__ w3, const float* __restrict__ b3v,
        float* __restrict__ out)
{
    __shared__ float As[16][64];
    __shared__ float Bs[16][128];
    __shared__ float h2bs[64][130];
    __shared__ float w3s[5*128];
    int tid = threadIdx.x;
    int m0 = blockIdx.x*64;
    int tx = tid & 15, ty = tid >> 4;

    for (int i = tid; i < 5*128; i += 256) w3s[i] = w3[i];

    float acc[4][8];
    #pragma unroll
    for (int i = 0; i < 4; i++)
        #pragma unroll
        for (int j = 0; j < 8; j++) acc[i][j] = 0.f;

    for (int k0 = 0; k0 < H1_; k0 += 16){
        #pragma unroll
        for (int i = 0; i < 4; i++){
            int e = i*256 + tid;
            int r = e >> 4, kk = e & 15;
            As[kk][r] = g_h2a[(m0 + r)*H1_ + k0 + kk];
        }
        {
            int o  = tid >> 1;            // 0..127
            int kq = (tid & 1)*8;
            float4 w0 = *(const float4*)&W[o*H1_ + k0 + kq];
            float4 w1 = *(const float4*)&W[o*H1_ + k0 + kq + 4];
            Bs[kq+0][o]=w0.x; Bs[kq+1][o]=w0.y; Bs[kq+2][o]=w0.z; Bs[kq+3][o]=w0.w;
            Bs[kq+4][o]=w1.x; Bs[kq+5][o]=w1.y; Bs[kq+6][o]=w1.z; Bs[kq+7][o]=w1.w;
        }
        __syncthreads();
        #pragma unroll
        for (int kk = 0; kk < 16; kk++){
            float ra[4], rb[8];
            #pragma unroll
            for (int i = 0; i < 4; i++) ra[i] = As[kk][ty*4 + i];
            *(float4*)&rb[0] = *(const float4*)&Bs[kk][tx*8];
            *(float4*)&rb[4] = *(const float4*)&Bs[kk][tx*8 + 4];
            #pragma unroll
            for (int i = 0; i < 4; i++)
                #pragma unroll
                for (int j = 0; j < 8; j++)
                    acc[i][j] += ra[i]*rb[j];
        }
        __syncthreads();
    }
    // h2b -> smem (relu + bias)
    #pragma unroll
    for (int i = 0; i < 4; i++)
        #pragma unroll
        for (int j = 0; j < 8; j++){
            int o = tx*8 + j;
            h2bs[ty*4 + i][o] = fmaxf(acc[i][j] + bias[o], 0.f);
        }
    __syncthreads();

    // query: 4 threads per row, quad-reduce
    {
        int r = tid >> 2, q = tid & 3;
        int m = m0 + r;
        int t = m / N_, n = m % N_;
        #pragma unroll
        for (int c = 0; c < 5; c++){
            float p = 0.f;
            #pragma unroll
            for (int k = 0; k < 32; k++)
                p += h2bs[r][q*32 + k] * w3s[c*H1_ + q*32 + k];
            p += __shfl_xor_sync(0xffffffff, p, 1);
            p += __shfl_xor_sync(0xffffffff, p, 2);
            if (q == 0)
                out[OUT_QS + t*5*N_ + c*N_ + n] = sigmoidf_(p + b3v[c]);
        }
    }
}

// ---------------------------------------------------------------------------
extern "C" void kernel_launch(void* const* d_in, const int* in_sizes, int n_in,
                              void* d_out, int out_size)
{
    const float* nf       = (const float*)d_in[0];
    const float* adj      = (const float*)d_in[1];
    const float* fc1_w1   = (const float*)d_in[2];
    const float* fc1_b1   = (const float*)d_in[3];
    const float* fc1_w2   = (const float*)d_in[4];
    const float* fc1_b2   = (const float*)d_in[5];
    const float* fc1_w3   = (const float*)d_in[6];
    const float* fc1_b3   = (const float*)d_in[7];
    const float* weight_G = (const float*)d_in[8];
    const float* bias_G   = (const float*)d_in[9];
    const float* fc2_w1   = (const float*)d_in[10];
    const float* fc2_b1   = (const float*)d_in[11];
    const float* fc2_w2   = (const float*)d_in[12];
    const float* fc2_b2   = (const float*)d_in[13];
    const float* fc2_w3   = (const float*)d_in[14];
    const float* fc2_b3   = (const float*)d_in[15];

    float* out       = (float*)d_out;
    float* score_out = out + OUT_SCORE;

    size_t smem_pair = (size_t)(3*128*ROWH + 2*H0_)*sizeof(__half)
                     + (size_t)(3*H1_)*sizeof(float);
    cudaFuncSetAttribute(k_pair, cudaFuncAttributeMaxDynamicSharedMemorySize, (int)smem_pair);

    k_pre<<<dim3(8, 25), 256>>>(nf, fc1_w1, fc1_b1, fc1_w2);
    k_pair<<<TNROWS/2, 256, smem_pair>>>(fc1_b2, fc1_w3, fc1_b3, adj, score_out);
    k_support<<<dim3(GD_/64, (TNROWS + 63)/64), 256>>>(nf, weight_G, out);
    k_wl<<<dim3(GD_/64, (N_ + 63)/64, T_), 256>>>(bias_G, out);
    k_fc2a<<<dim3(H1_/64, (TNROWS + 63)/64), 256>>>(fc2_w1, fc2_b1);
    k_fc2bq<<<TNROWS/64, 256>>>(fc2_w2, fc2_b2, fc2_w3, fc2_b3, out);
}

// round 16
// speedup vs baseline: 1.1661x; 1.0052x over previous
#include <cuda_runtime.h>
#include <cuda_fp16.h>
#include <math.h>

#define T_  4
#define N_  400
#define S_  395
#define D_  128
#define H0_ 256
#define H1_ 128
#define GD_ 768
#define TNROWS (T_*N_)           // 1600

// output layout: [wl_mean (400*768)] [learned_score (4*400*400)] [query^T (4*5*400)]
#define OUT_SCORE (N_*GD_)               // 307200
#define OUT_QS    (OUT_SCORE + T_*N_*N_) // 947200

#define ROWH 264                 // padded half-row stride for k_pair ldmatrix tiles

__device__ __half g_ABh[TNROWS*H0_];     // fp16(A + b1)
__device__ __half g_Bh [TNROWS*H0_];     // fp16(B)
__device__ __half g_W2h[H1_*H0_];        // fp16(fc1_w2)
__device__ __half g_ladjH[T_*N_*N_];     // fp16(learned_adj)
__device__ __half g_nfH[TNROWS*D_];      // hi/lo split of node_feat
__device__ __half g_nfL[TNROWS*D_];
__device__ __half g_WgH[GD_*GD_];        // hi/lo split of weight_G
__device__ __half g_WgL[GD_*GD_];
__device__ __half g_W1H[H1_*GD_];        // hi/lo split of fc2_w1
__device__ __half g_W1L[H1_*GD_];
__device__ __half g_supH[TNROWS*GD_];
__device__ __half g_supL[TNROWS*GD_];
__device__ __half g_wlH[TNROWS*GD_];     // hi/lo split of wl
__device__ __half g_wlL[TNROWS*GD_];
__device__ float  g_h2a[TNROWS*H1_];
__device__ float  g_h2b[TNROWS*H1_];

__device__ __forceinline__ float sigmoidf_(float x){ return 1.0f/(1.0f + __expf(-x)); }

__device__ __forceinline__ unsigned smem_u32(const void* p){
    unsigned a;
    asm("{ .reg .u64 t; cvta.to.shared.u64 t, %1; cvt.u32.u64 %0, t; }" : "=r"(a) : "l"(p));
    return a;
}
__device__ __forceinline__ void ldsm_x4(unsigned* r, unsigned addr){
    asm volatile("ldmatrix.sync.aligned.m8n8.x4.shared.b16 {%0,%1,%2,%3}, [%4];"
        : "=r"(r[0]), "=r"(r[1]), "=r"(r[2]), "=r"(r[3]) : "r"(addr));
}
__device__ __forceinline__ void ldsm_x4_t(unsigned* r, unsigned addr){
    asm volatile("ldmatrix.sync.aligned.m8n8.x4.trans.shared.b16 {%0,%1,%2,%3}, [%4];"
        : "=r"(r[0]), "=r"(r[1]), "=r"(r[2]), "=r"(r[3]) : "r"(addr));
}
__device__ __forceinline__ void mma16816(float* d, const unsigned* a, const unsigned* b){
    asm volatile("mma.sync.aligned.m16n8k16.row.col.f32.f16.f16.f32 "
        "{%0,%1,%2,%3},{%4,%5,%6,%7},{%8,%9},{%0,%1,%2,%3};"
        : "+f"(d[0]), "+f"(d[1]), "+f"(d[2]), "+f"(d[3])
        : "r"(a[0]), "r"(a[1]), "r"(a[2]), "r"(a[3]), "r"(b[0]), "r"(b[1]));
}
__device__ __forceinline__ void split2(float x, __half& h, __half& l){
    h = __float2half_rn(x);
    l = __float2half_rn(x - __half2float(h));
}
__device__ __forceinline__ void mma_m16n32_t(float d[4][4], unsigned Asu, unsigned Bsu,
                                             int lane, int warp_m, int warp_n, int PA, int PB)
{
    int ar = lane & 15, ac = (lane >> 4) * 8;
    int bk = ((lane >> 3) & 1) * 8 + (lane & 7);
    int bj = ((lane >> 4) & 1) * 8;
    #pragma unroll
    for (int ks = 0; ks < 4; ks++){
        unsigned a[4], b[2][4];
        ldsm_x4(a, Asu + (unsigned)(((warp_m*16 + ar)*PA + ks*16 + ac)*2));
        #pragma unroll
        for (int nb = 0; nb < 2; nb++)
            ldsm_x4_t(b[nb], Bsu + (unsigned)(((ks*16 + bk)*PB + warp_n*32 + nb*16 + bj)*2));
        #pragma unroll
        for (int nb = 0; nb < 2; nb++){
            mma16816(d[nb*2+0], a, &b[nb][0]);
            mma16816(d[nb*2+1], a, &b[nb][2]);
        }
    }
}
__device__ __forceinline__ void mma_m16n32_n(float d[4][4], unsigned Asu, unsigned Bsu,
                                             int lane, int warp_m, int warp_n, int PA, int PB)
{
    int ar = lane & 15, ac = (lane >> 4) * 8;
    int bg = lane >> 3;
    int bj = ((bg >= 2) ? 8 : 0) + (lane & 7);
    int bk2 = (bg & 1) * 8;
    #pragma unroll
    for (int ks = 0; ks < 4; ks++){
        unsigned a[4], b[2][4];
        ldsm_x4(a, Asu + (unsigned)(((warp_m*16 + ar)*PA + ks*16 + ac)*2));
        #pragma unroll
        for (int nb = 0; nb < 2; nb++)
            ldsm_x4(b[nb], Bsu + (unsigned)(((warp_n*32 + nb*16 + bj)*PB + ks*16 + bk2)*2));
        #pragma unroll
        for (int nb = 0; nb < 2; nb++){
            mma16816(d[nb*2+0], a, &b[nb][0]);
            mma16816(d[nb*2+1], a, &b[nb][2]);
        }
    }
}

// ---------------------------------------------------------------------------
// Kernel 0: elementwise hi/lo pre-split of nf, weight_G, fc2_w1
// ---------------------------------------------------------------------------
__global__ void k_split(const float* __restrict__ nf, const float* __restrict__ Wg,
                        const float* __restrict__ W1)
{
    int i = blockIdx.x*256 + threadIdx.x;
    if (i < TNROWS*D_){ __half h,l; split2(nf[i],h,l); g_nfH[i]=h; g_nfL[i]=l; }
    if (i < GD_*GD_)  { __half h,l; split2(Wg[i],h,l); g_WgH[i]=h; g_WgL[i]=l; }
    if (i < H1_*GD_)  { __half h,l; split2(W1[i],h,l); g_W1H[i]=h; g_W1L[i]=l; }
}

// ---------------------------------------------------------------------------
// Kernel 1: A/B precompute -> fp16 g_ABh (A+b1), g_Bh; + W2->fp16 fold
// ---------------------------------------------------------------------------
__global__ void k_pre(const float* __restrict__ nf, const float* __restrict__ w1,
                      const float* __restrict__ b1, const float* __restrict__ w2)
{
    __shared__ float As[16][64];
    __shared__ float Bs[16][64];
    int tid = threadIdx.x;
    int m0 = blockIdx.y*64, h0 = blockIdx.x*64;
    int tx = tid & 15, ty = tid >> 4;

    {
        int i = (blockIdx.y*8 + blockIdx.x)*256 + tid;
        if (i < H1_*H0_) g_W2h[i] = __float2half_rn(w2[i]);
    }

    float acc[4][4] = {};
    for (int k0 = 0; k0 < D_; k0 += 16){
        #pragma unroll
        for (int i = 0; i < 4; i++){
            int e = i*256 + tid;
            int r = e >> 4, kk = e & 15;
            As[kk][r] = nf[(m0 + r)*D_ + k0 + kk];
        }
        {
            int o  = tid >> 2;
            int kq = (tid & 3)*4;
            int hp = h0 + o;
            const float* src = w1 + (hp & 255)*(2*D_) + (hp >> 8)*D_ + k0 + kq;
            float4 w = *(const float4*)src;
            Bs[kq+0][o] = w.x; Bs[kq+1][o] = w.y; Bs[kq+2][o] = w.z; Bs[kq+3][o] = w.w;
        }
        __syncthreads();
        #pragma unroll
        for (int kk = 0; kk < 16; kk++){
            float ra[4], rb[4];
            #pragma unroll
            for (int i = 0; i < 4; i++) ra[i] = As[kk][ty*4 + i];
            #pragma unroll
            for (int jj = 0; jj < 4; jj++) rb[jj] = Bs[kk][tx*4 + jj];
            #pragma unroll
            for (int i = 0; i < 4; i++)
                #pragma unroll
                for (int jj = 0; jj < 4; jj++)
                    acc[i][jj] += ra[i]*rb[jj];
        }
        __syncthreads();
    }
    #pragma unroll
    for (int i = 0; i < 4; i++)
        #pragma unroll
        for (int jj = 0; jj < 4; jj++){
            int hp = h0 + tx*4 + jj;
            int row = m0 + ty*4 + i;
            float v = acc[i][jj];
            if (hp < H0_) g_ABh[row*H0_ + hp]         = __float2half_rn(v + b1[hp]);
            else          g_Bh [row*H0_ + (hp - 256)] = __float2half_rn(v);
        }
}

// ---------------------------------------------------------------------------
// Kernel 2: pairwise MLP (R12 exact: 2 'a' rows/block, shared raw-B tile,
// m16 tail for b0=384)
// ---------------------------------------------------------------------------
__global__ void __launch_bounds__(256, 1)
k_pair(const float* __restrict__ b2v, const float* __restrict__ w3,
       const float* __restrict__ b3v, float* __restrict__ score_out)
{
    extern __shared__ char smraw[];
    __half* h1s = (__half*)smraw;                 // 128*ROWH
    __half* W2s = h1s + 128*ROWH;                 // 128*ROWH
    __half* rBs = W2s + 128*ROWH;                 // 128*ROWH (raw B tile)
    __half* Ar0 = rBs + 128*ROWH;                 // 256
    __half* Ar1 = Ar0 + H0_;                      // 256
    float*  sred = (float*)(Ar1 + H0_);           // 128
    float*  b2s  = sred + H1_;                    // 128
    float*  w3s  = b2s + H1_;                     // 128

    int a0 = blockIdx.x*2, a1 = a0 + 1;
    int t  = a0 / N_;
    int tid = threadIdx.x, lane = tid & 31, wid = tid >> 5;
    int warp_n = wid & 3, warp_m = wid >> 2;

    #pragma unroll
    for (int i = 0; i < 16; i++){
        int idx = i*256 + tid;
        int row = idx >> 5, c8 = idx & 31;
        *(uint4*)&W2s[row*ROWH + c8*8] = *(const uint4*)&g_W2h[row*H0_ + c8*8];
    }
    Ar0[tid] = g_ABh[a0*H0_ + tid];
    Ar1[tid] = g_ABh[a1*H0_ + tid];
    if (tid < H1_){ b2s[tid] = b2v[tid]; w3s[tid] = w3[tid]; }
    float b3 = b3v[0];

    unsigned h1u = smem_u32(h1s);
    unsigned w2u = smem_u32(W2s);

    int a_trow  = lane & 15;
    int a_tcol8 = (lane >> 4) * 8;
    int b_g     = lane >> 3;
    int b_joff  = ((b_g >= 2) ? 8 : 0) + (lane & 7);
    int b_koff  = (b_g & 1) * 8;

    unsigned aA[4], bA[2];
    #pragma unroll
    for (int mt = 0; mt < 4; mt++)
        aA[mt] = h1u + ((warp_m*64 + mt*16 + a_trow)*ROWH + a_tcol8)*2;
    #pragma unroll
    for (int nb = 0; nb < 2; nb++)
        bA[nb] = w2u + ((warp_n*32 + nb*16 + b_joff)*ROWH + b_koff)*2;

    const __half2 z2 = __float2half2_rn(0.f);

    for (int b0 = 0; b0 < 384; b0 += 128){
        __syncthreads();
        #pragma unroll
        for (int i = 0; i < 16; i++){
            int idx = i*256 + tid;
            int row = idx >> 5, c8 = idx & 31;
            uint4 v = *(const uint4*)&g_Bh[((size_t)(t*N_ + b0 + row))*H0_ + c8*8];
            *(uint4*)&rBs[row*ROWH + c8*8] = v;
            const __half2* vp = (const __half2*)&v;
            uint4 o; __half2* op = (__half2*)&o;
            #pragma unroll
            for (int q = 0; q < 4; q++)
                op[q] = __hmax2(__hadd2(vp[q], *(const __half2*)&Ar0[c8*8 + q*2]), z2);
            *(uint4*)&h1s[row*ROWH + c8*8] = o;
        }
        if (tid < H1_) sred[tid] = 0.f;
        __syncthreads();

        {
            float d[4][4][4];
            #pragma unroll
            for (int i=0;i<4;i++)
                #pragma unroll
                for (int j=0;j<4;j++)
                    #pragma unroll
                    for (int v=0;v<4;v++) d[i][j][v]=0.f;
            #pragma unroll 4
            for (int ks = 0; ks < 16; ks++){
                unsigned afr[4][4], bfr[2][4];
                #pragma unroll
                for (int mt = 0; mt < 4; mt++) ldsm_x4(afr[mt], aA[mt] + ks*32);
                #pragma unroll
                for (int nb = 0; nb < 2; nb++) ldsm_x4(bfr[nb], bA[nb] + ks*32);
                #pragma unroll
                for (int mt = 0; mt < 4; mt++)
                    #pragma unroll
                    for (int nb = 0; nb < 2; nb++){
                        mma16816(d[mt][nb*2+0], afr[mt], &bfr[nb][0]);
                        mma16816(d[mt][nb*2+1], afr[mt], &bfr[nb][2]);
                    }
            }
            #pragma unroll
            for (int mt = 0; mt < 4; mt++){
                #pragma unroll
                for (int h = 0; h < 2; h++){
                    float part = 0.f;
                    #pragma unroll
                    for (int n8 = 0; n8 < 4; n8++){
                        #pragma unroll
                        for (int c = 0; c < 2; c++){
                            int j = warp_n*32 + n8*8 + (lane & 3)*2 + c;
                            part += fmaxf(d[mt][n8][h*2 + c] + b2s[j], 0.f) * w3s[j];
                        }
                    }
                    part += __shfl_xor_sync(0xffffffff, part, 1);
                    part += __shfl_xor_sync(0xffffffff, part, 2);
                    if ((lane & 3) == 0)
                        atomicAdd(&sred[warp_m*64 + mt*16 + (lane >> 2) + h*8], part);
                }
            }
        }
        __syncthreads();
        if (tid < H1_){
            score_out[a0*N_ + b0 + tid] = sigmoidf_(sred[tid] + b3);
            sred[tid] = 0.f;
        }
        #pragma unroll
        for (int i = 0; i < 16; i++){
            int idx = i*256 + tid;
            int row = idx >> 5, c8 = idx & 31;
            uint4 v = *(const uint4*)&rBs[row*ROWH + c8*8];
            const __half2* vp = (const __half2*)&v;
            uint4 o; __half2* op = (__half2*)&o;
            #pragma unroll
            for (int q = 0; q < 4; q++)
                op[q] = __hmax2(__hadd2(vp[q], *(const __half2*)&Ar1[c8*8 + q*2]), z2);
            *(uint4*)&h1s[row*ROWH + c8*8] = o;
        }
        __syncthreads();

        {
            float d[4][4][4];
            #pragma unroll
            for (int i=0;i<4;i++)
                #pragma unroll
                for (int j=0;j<4;j++)
                    #pragma unroll
                    for (int v=0;v<4;v++) d[i][j][v]=0.f;
            #pragma unroll 4
            for (int ks = 0; ks < 16; ks++){
                unsigned afr[4][4], bfr[2][4];
                #pragma unroll
                for (int mt = 0; mt < 4; mt++) ldsm_x4(afr[mt], aA[mt] + ks*32);
                #pragma unroll
                for (int nb = 0; nb < 2; nb++) ldsm_x4(bfr[nb], bA[nb] + ks*32);
                #pragma unroll
                for (int mt = 0; mt < 4; mt++)
                    #pragma unroll
                    for (int nb = 0; nb < 2; nb++){
                        mma16816(d[mt][nb*2+0], afr[mt], &bfr[nb][0]);
                        mma16816(d[mt][nb*2+1], afr[mt], &bfr[nb][2]);
                    }
            }
            #pragma unroll
            for (int mt = 0; mt < 4; mt++){
                #pragma unroll
                for (int h = 0; h < 2; h++){
                    float part = 0.f;
                    #pragma unroll
                    for (int n8 = 0; n8 < 4; n8++){
                        #pragma unroll
                        for (int c = 0; c < 2; c++){
                            int j = warp_n*32 + n8*8 + (lane & 3)*2 + c;
                            part += fmaxf(d[mt][n8][h*2 + c] + b2s[j], 0.f) * w3s[j];
                        }
                    }
                    part += __shfl_xor_sync(0xffffffff, part, 1);
                    part += __shfl_xor_sync(0xffffffff, part, 2);
                    if ((lane & 3) == 0)
                        atomicAdd(&sred[warp_m*64 + mt*16 + (lane >> 2) + h*8], part);
                }
            }
        }
        __syncthreads();
        if (tid < H1_)
            score_out[a1*N_ + b0 + tid] = sigmoidf_(sred[tid] + b3);
    }

    // tail tile b0 = 384 (16 rows)
    {
        const int b0 = 384;
        __syncthreads();
        #pragma unroll
        for (int i = 0; i < 2; i++){
            int idx = i*256 + tid;
            int row = idx >> 5, c8 = idx & 31;
            uint4 v = *(const uint4*)&g_Bh[((size_t)(t*N_ + b0 + row))*H0_ + c8*8];
            *(uint4*)&rBs[row*ROWH + c8*8] = v;
            const __half2* vp = (const __half2*)&v;
            uint4 o; __half2* op = (__half2*)&o;
            #pragma unroll
            for (int q = 0; q < 4; q++)
                op[q] = __hmax2(__hadd2(vp[q], *(const __half2*)&Ar0[c8*8 + q*2]), z2);
            *(uint4*)&h1s[row*ROWH + c8*8] = o;
        }
        if (tid < H1_) sred[tid] = 0.f;
        __syncthreads();

        if (warp_m == 0){
            float d[4][4];
            #pragma unroll
            for (int j=0;j<4;j++)
                #pragma unroll
                for (int v=0;v<4;v++) d[j][v]=0.f;
            #pragma unroll 4
            for (int ks = 0; ks < 16; ks++){
                unsigned afr[4], bfr[2][4];
                ldsm_x4(afr, h1u + ((a_trow)*ROWH + a_tcol8)*2 + ks*32);
                #pragma unroll
                for (int nb = 0; nb < 2; nb++) ldsm_x4(bfr[nb], bA[nb] + ks*32);
                #pragma unroll
                for (int nb = 0; nb < 2; nb++){
                    mma16816(d[nb*2+0], afr, &bfr[nb][0]);
                    mma16816(d[nb*2+1], afr, &bfr[nb][2]);
                }
            }
            #pragma unroll
            for (int h = 0; h < 2; h++){
                float part = 0.f;
                #pragma unroll
                for (int n8 = 0; n8 < 4; n8++){
                    #pragma unroll
                    for (int c = 0; c < 2; c++){
                        int j = warp_n*32 + n8*8 + (lane & 3)*2 + c;
                        part += fmaxf(d[n8][h*2 + c] + b2s[j], 0.f) * w3s[j];
                    }
                }
                part += __shfl_xor_sync(0xffffffff, part, 1);
                part += __shfl_xor_sync(0xffffffff, part, 2);
                if ((lane & 3) == 0)
                    atomicAdd(&sred[(lane >> 2) + h*8], part);
            }
        }
        __syncthreads();
        if (tid < 16)
            score_out[a0*N_ + b0 + tid] = sigmoidf_(sred[tid] + b3);
        if (tid < H1_) sred[tid] = 0.f;
        #pragma unroll
        for (int i = 0; i < 2; i++){
            int idx = i*256 + tid;
            int row = idx >> 5, c8 = idx & 31;
            uint4 v = *(const uint4*)&rBs[row*ROWH + c8*8];
            const __half2* vp = (const __half2*)&v;
            uint4 o; __half2* op = (__half2*)&o;
            #pragma unroll
            for (int q = 0; q < 4; q++)
                op[q] = __hmax2(__hadd2(vp[q], *(const __half2*)&Ar1[c8*8 + q*2]), z2);
            *(uint4*)&h1s[row*ROWH + c8*8] = o;
        }
        __syncthreads();

        if (warp_m == 0){
            float d[4][4];
            #pragma unroll
            for (int j=0;j<4;j++)
                #pragma unroll
                for (int v=0;v<4;v++) d[j][v]=0.f;
            #pragma unroll 4
            for (int ks = 0; ks < 16; ks++){
                unsigned afr[4], bfr[2][4];
                ldsm_x4(afr, h1u + ((a_trow)*ROWH + a_tcol8)*2 + ks*32);
                #pragma unroll
                for (int nb = 0; nb < 2; nb++) ldsm_x4(bfr[nb], bA[nb] + ks*32);
                #pragma unroll
                for (int nb = 0; nb < 2; nb++){
                    mma16816(d[nb*2+0], afr, &bfr[nb][0]);
                    mma16816(d[nb*2+1], afr, &bfr[nb][2]);
                }
            }
            #pragma unroll
            for (int h = 0; h < 2; h++){
                float part = 0.f;
                #pragma unroll
                for (int n8 = 0; n8 < 4; n8++){
                    #pragma unroll
                    for (int c = 0; c < 2; c++){
                        int j = warp_n*32 + n8*8 + (lane & 3)*2 + c;
                        part += fmaxf(d[n8][h*2 + c] + b2s[j], 0.f) * w3s[j];
                    }
                }
                part += __shfl_xor_sync(0xffffffff, part, 1);
                part += __shfl_xor_sync(0xffffffff, part, 2);
                if ((lane & 3) == 0)
                    atomicAdd(&sred[(lane >> 2) + h*8], part);
            }
        }
        __syncthreads();
        if (tid < 16)
            score_out[a1*N_ + b0 + tid] = sigmoidf_(sred[tid] + b3);
    }
}

// ---------------------------------------------------------------------------
// Kernel 2b: learned_adj -> fp16
// ---------------------------------------------------------------------------
__global__ void k_ladj(const float* __restrict__ adj, const float* __restrict__ score)
{
    int idx = blockIdx.x*256 + threadIdx.x;
    if (idx >= T_*N_*N_) return;
    int t = idx / (N_*N_);
    int r = idx % (N_*N_);
    int n = r / N_, m = r % N_;
    float v = score[idx];
    if (n < S_ && m < S_)
        v = (adj[(t*S_ + n)*S_ + m] > 0.f) ? 1.f : -v;
    g_ladjH[idx] = __float2half_rn(v);
}

// ---------------------------------------------------------------------------
// Kernel 3: support (hi/lo split, 3 passes), 64x64 tiles, PRE-SPLIT operands
// ---------------------------------------------------------------------------
__global__ void __launch_bounds__(256)
k_support()
{
    __shared__ __align__(16) __half Ah[64*72];
    __shared__ __align__(16) __half Al[64*72];
    __shared__ __align__(16) __half Bh[64*72];
    __shared__ __align__(16) __half Bl[64*72];
    int tid = threadIdx.x, lane = tid & 31, wid = tid >> 5;
    int warp_m = wid >> 1, warp_n = wid & 1;
    int o0 = blockIdx.x*64, m0 = blockIdx.y*64;
    unsigned Ahu = smem_u32(Ah), Alu = smem_u32(Al);
    unsigned Bhu = smem_u32(Bh), Blu = smem_u32(Bl);
    float d[4][4] = {};

    for (int k0 = 0; k0 < GD_; k0 += 64){
        #pragma unroll
        for (int i = 0; i < 2; i++){
            int idx = i*256 + tid;
            int row = idx >> 3, c8 = idx & 7;
            int m = m0 + row, f = k0 + c8*8;
            uint4 vh = make_uint4(0u,0u,0u,0u);
            uint4 vl = make_uint4(0u,0u,0u,0u);
            if (m < TNROWS){
                int tt = m / N_, n = m % N_;
                int node = (f < D_) ? n : (S_ + (f >> 7) - 1);
                size_t src = (size_t)(tt*N_ + node)*D_ + (f & 127);
                vh = *(const uint4*)&g_nfH[src];
                vl = *(const uint4*)&g_nfL[src];
            }
            *(uint4*)&Ah[row*72 + c8*8] = vh;
            *(uint4*)&Al[row*72 + c8*8] = vl;
        }
        #pragma unroll
        for (int i = 0; i < 2; i++){
            int idx = i*256 + tid;
            int row = idx >> 3, c8 = idx & 7;
            size_t src = (size_t)(k0 + row)*GD_ + o0 + c8*8;
            *(uint4*)&Bh[row*72 + c8*8] = *(const uint4*)&g_WgH[src];
            *(uint4*)&Bl[row*72 + c8*8] = *(const uint4*)&g_WgL[src];
        }
        __syncthreads();
        mma_m16n32_t(d, Ahu, Bhu, lane, warp_m, warp_n, 72, 72);
        mma_m16n32_t(d, Ahu, Blu, lane, warp_m, warp_n, 72, 72);
        mma_m16n32_t(d, Alu, Bhu, lane, warp_m, warp_n, 72, 72);
        __syncthreads();
    }
    #pragma unroll
    for (int n8 = 0; n8 < 4; n8++)
        #pragma unroll
        for (int v = 0; v < 4; v++){
            int row = m0 + warp_m*16 + (lane >> 2) + (v >> 1)*8;
            int col = o0 + warp_n*32 + n8*8 + (lane & 3)*2 + (v & 1);
            if (row < TNROWS){
                __half h, l;
                split2(d[n8][v], h, l);
                g_supH[row*GD_ + col] = h;
                g_supL[row*GD_ + col] = l;
            }
        }
}

// ---------------------------------------------------------------------------
// Kernel 4: wl = relu(ladj·sup + biasG) -> hi/lo fp16 pair
// ---------------------------------------------------------------------------
__global__ void __launch_bounds__(256)
k_wl(const float* __restrict__ biasG)
{
    __shared__ __align__(16) __half As[64*72];
    __shared__ __align__(16) __half Bh[64*72];
    __shared__ __align__(16) __half Bl[64*72];
    int tid = threadIdx.x, lane = tid & 31, wid = tid >> 5;
    int warp_m = wid >> 1, warp_n = wid & 1;
    int o0 = blockIdx.x*64, m0 = blockIdx.y*64, t = blockIdx.z;
    unsigned Asu = smem_u32(As), Bhu = smem_u32(Bh), Blu = smem_u32(Bl);
    float d[4][4] = {};

    for (int k0 = 0; k0 < N_; k0 += 64){
        #pragma unroll
        for (int i = 0; i < 2; i++){
            int idx = i*256 + tid;
            int row = idx >> 3, c8 = idx & 7;
            int n = m0 + row, k = k0 + c8*8;
            uint4 v = make_uint4(0u,0u,0u,0u);
            if (n < N_ && k < N_)
                v = *(const uint4*)&g_ladjH[(t*N_ + n)*N_ + k];
            *(uint4*)&As[row*72 + c8*8] = v;
        }
        #pragma unroll
        for (int i = 0; i < 2; i++){
            int idx = i*256 + tid;
            int row = idx >> 3, c8 = idx & 7;
            int k = k0 + row;
            uint4 vh = make_uint4(0u,0u,0u,0u);
            uint4 vl = make_uint4(0u,0u,0u,0u);
            if (k < N_){
                vh = *(const uint4*)&g_supH[(t*N_ + k)*GD_ + o0 + c8*8];
                vl = *(const uint4*)&g_supL[(t*N_ + k)*GD_ + o0 + c8*8];
            }
            *(uint4*)&Bh[row*72 + c8*8] = vh;
            *(uint4*)&Bl[row*72 + c8*8] = vl;
        }
        __syncthreads();
        mma_m16n32_t(d, Asu, Bhu, lane, warp_m, warp_n, 72, 72);
        mma_m16n32_t(d, Asu, Blu, lane, warp_m, warp_n, 72, 72);
        __syncthreads();
    }
    #pragma unroll
    for (int n8 = 0; n8 < 4; n8++)
        #pragma unroll
        for (int v = 0; v < 4; v++){
            int n = m0 + warp_m*16 + (lane >> 2) + (v >> 1)*8;
            int o = o0 + warp_n*32 + n8*8 + (lane & 3)*2 + (v & 1);
            if (n < N_){
                float val = fmaxf(d[n8][v] + biasG[o], 0.f);
                __half h, l;
                split2(val, h, l);
                g_wlH[(t*N_ + n)*GD_ + o] = h;
                g_wlL[(t*N_ + n)*GD_ + o] = l;
            }
        }
}

// ---------------------------------------------------------------------------
// Kernel 5: wl mean over t -> out[0 .. 307200)
// ---------------------------------------------------------------------------
__global__ void k_mean(float* __restrict__ out)
{
    int i = blockIdx.x*blockDim.x + threadIdx.x;
    if (i < N_*GD_){
        float s = 0.f;
        #pragma unroll
        for (int t = 0; t < T_; t++){
            int idx = i + t*N_*GD_;
            s += __half2float(g_wlH[idx]) + __half2float(g_wlL[idx]);
        }
        out[i] = 0.25f * s;
    }
}

// ---------------------------------------------------------------------------
// Kernel 6: h2a = relu(wl·W1^T + b1), split MMA (3 passes), PRE-SPLIT operands
// ---------------------------------------------------------------------------
__global__ void __launch_bounds__(256)
k_fc2a(const float* __restrict__ bias)
{
    __shared__ __align__(16) __half Ah[64*72];
    __shared__ __align__(16) __half Al[64*72];
    __shared__ __align__(16) __half Bh[64*72];
    __shared__ __align__(16) __half Bl[64*72];
    int tid = threadIdx.x, lane = tid & 31, wid = tid >> 5;
    int warp_m = wid >> 1, warp_n = wid & 1;
    int o0 = blockIdx.x*64, m0 = blockIdx.y*64;
    unsigned Ahu = smem_u32(Ah), Alu = smem_u32(Al);
    unsigned Bhu = smem_u32(Bh), Blu = smem_u32(Bl);
    float d[4][4] = {};

    for (int k0 = 0; k0 < GD_; k0 += 64){
        #pragma unroll
        for (int i = 0; i < 2; i++){
            int idx = i*256 + tid;
            int row = idx >> 3, c8 = idx & 7;
            int m = m0 + row;
            uint4 vh = make_uint4(0u,0u,0u,0u);
            uint4 vl = make_uint4(0u,0u,0u,0u);
            if (m < TNROWS){
                size_t src = (size_t)m*GD_ + k0 + c8*8;
                vh = *(const uint4*)&g_wlH[src];
                vl = *(const uint4*)&g_wlL[src];
            }
            *(uint4*)&Ah[row*72 + c8*8] = vh;
            *(uint4*)&Al[row*72 + c8*8] = vl;
        }
        #pragma unroll
        for (int i = 0; i < 2; i++){
            int idx = i*256 + tid;
            int row = idx >> 3, c8 = idx & 7;
            size_t src = (size_t)(o0 + row)*GD_ + k0 + c8*8;
            *(uint4*)&Bh[row*72 + c8*8] = *(const uint4*)&g_W1H[src];
            *(uint4*)&Bl[row*72 + c8*8] = *(const uint4*)&g_W1L[src];
        }
        __syncthreads();
        mma_m16n32_n(d, Ahu, Bhu, lane, warp_m, warp_n, 72, 72);
        mma_m16n32_n(d, Ahu, Blu, lane, warp_m, warp_n, 72, 72);
        mma_m16n32_n(d, Alu, Bhu, lane, warp_m, warp_n, 72, 72);
        __syncthreads();
    }
    #pragma unroll
    for (int n8 = 0; n8 < 4; n8++)
        #pragma unroll
        for (int v = 0; v < 4; v++){
            int row = m0 + warp_m*16 + (lane >> 2) + (v >> 1)*8;
            int col = o0 + warp_n*32 + n8*8 + (lane & 3)*2 + (v & 1);
            if (row < TNROWS)
                g_h2a[row*H1_ + col] = fmaxf(d[n8][v] + bias[col], 0.f);
        }
}

// ---------------------------------------------------------------------------
// Kernel 7: h2b = relu(h2a·W2^T + b)  fp32 SIMT  M=1600,K=128,O=128
// ---------------------------------------------------------------------------
__global__ void k_fc2b(const float* __restrict__ W, const float* __restrict__ bias)
{
    __shared__ float As[16][64];
    __shared__ float Bs[16][64];
    int tid = threadIdx.x;
    int m0 = blockIdx.y*64, o0 = blockIdx.x*64;
    int tx = tid & 15, ty = tid >> 4;
    float acc[4][4] = {};
    for (int k0 = 0; k0 < H1_; k0 += 16){
        #pragma unroll
        for (int i = 0; i < 4; i++){
            int e = i*256 + tid;
            int r = e >> 4, kk = e & 15;
            As[kk][r] = g_h2a[(m0 + r)*H1_ + k0 + kk];
        }
        {
            int o  = tid >> 2;
            int kq = (tid & 3)*4;
            float4 w = *(const float4*)&W[(o0 + o)*H1_ + k0 + kq];
            Bs[kq+0][o] = w.x; Bs[kq+1][o] = w.y; Bs[kq+2][o] = w.z; Bs[kq+3][o] = w.w;
        }
        __syncthreads();
        #pragma unroll
        for (int kk = 0; kk < 16; kk++){
            float ra[4], rb[4];
            #pragma unroll
            for (int i = 0; i < 4; i++) ra[i] = As[kk][ty*4 + i];
            #pragma unroll
            for (int jj = 0; jj < 4; jj++) rb[jj] = Bs[kk][tx*4 + jj];
            #pragma unroll
            for (int i = 0; i < 4; i++)
                #pragma unroll
                for (int jj = 0; jj < 4; jj++)
                    acc[i][jj] += ra[i]*rb[jj];
        }
        __syncthreads();
    }
    #pragma unroll
    for (int i = 0; i < 4; i++)
        #pragma unroll
        for (int jj = 0; jj < 4; jj++){
            int o = o0 + tx*4 + jj;
            g_h2b[(m0 + ty*4 + i)*H1_ + o] = fmaxf(acc[i][jj] + bias[o], 0.f);
        }
}

// ---------------------------------------------------------------------------
// Kernel 8: query[t,c,n] = sigmoid( h2b[t,n,:]·w3[c,:] + b3[c] )
// ---------------------------------------------------------------------------
__global__ void k_query(const float* __restrict__ w3, const float* __restrict__ b3,
                        float* __restrict__ out)
{
    int idx = blockIdx.x*blockDim.x + threadIdx.x;
    if (idx >= TNROWS*5) return;
    int row = idx / 5, c = idx % 5;
    const float* h = g_h2b + row*H1_;
    const float* w = w3 + c*H1_;
    float s = 0.f;
    #pragma unroll 8
    for (int k = 0; k < H1_; k++) s += h[k]*w[k];
    int t = row / N_, n = row % N_;
    out[OUT_QS + t*5*N_ + c*N_ + n] = sigmoidf_(s + b3[c]);
}

// ---------------------------------------------------------------------------
extern "C" void kernel_launch(void* const* d_in, const int* in_sizes, int n_in,
                              void* d_out, int out_size)
{
    const float* nf       = (const float*)d_in[0];
    const float* adj      = (const float*)d_in[1];
    const float* fc1_w1   = (const float*)d_in[2];
    const float* fc1_b1   = (const float*)d_in[3];
    const float* fc1_w2   = (const float*)d_in[4];
    const float* fc1_b2   = (const float*)d_in[5];
    const float* fc1_w3   = (const float*)d_in[6];
    const float* fc1_b3   = (const float*)d_in[7];
    const float* weight_G = (const float*)d_in[8];
    const float* bias_G   = (const float*)d_in[9];
    const float* fc2_w1   = (const float*)d_in[10];
    const float* fc2_b1   = (const float*)d_in[11];
    const float* fc2_w2   = (const float*)d_in[12];
    const float* fc2_b2   = (const float*)d_in[13];
    const float* fc2_w3   = (const float*)d_in[14];
    const float* fc2_b3   = (const float*)d_in[15];

    float* out       = (float*)d_out;
    float* score_out = out + OUT_SCORE;

    size_t smem_pair = (size_t)(3*128*ROWH + 2*H0_)*sizeof(__half)
                     + (size_t)(3*H1_)*sizeof(float);
    cudaFuncSetAttribute(k_pair, cudaFuncAttributeMaxDynamicSharedMemorySize, (int)smem_pair);

    k_pre<<<dim3(8, 25), 256>>>(nf, fc1_w1, fc1_b1, fc1_w2);
    k_split<<<(GD_*GD_ + 255)/256, 256>>>(nf, weight_G, fc2_w1);
    k_pair<<<TNROWS/2, 256, smem_pair>>>(fc1_b2, fc1_w3, fc1_b3, score_out);
    k_ladj<<<(T_*N_*N_ + 255)/256, 256>>>(adj, score_out);
    k_support<<<dim3(GD_/64, (TNROWS + 63)/64), 256>>>();
    k_wl<<<dim3(GD_/64, (N_ + 63)/64, T_), 256>>>(bias_G);
    k_mean<<<(N_*GD_ + 255)/256, 256>>>(out);
    k_fc2a<<<dim3(H1_/64, (TNROWS + 63)/64), 256>>>(fc2_b1);
    k_fc2b<<<dim3(H1_/64, TNROWS/64), 256>>>(fc2_w2, fc2_b2);
    k_query<<<(TNROWS*5 + 127)/128, 128>>>(fc2_w3, fc2_b3, out);
}

// round 17
// speedup vs baseline: 1.2542x; 1.0756x over previous
#include <cuda_runtime.h>
#include <cuda_fp16.h>
#include <math.h>

#define T_  4
#define N_  400
#define S_  395
#define D_  128
#define H0_ 256
#define H1_ 128
#define GD_ 768
#define TNROWS (T_*N_)           // 1600

// output layout: [wl_mean (400*768)] [learned_score (4*400*400)] [query^T (4*5*400)]
#define OUT_SCORE (N_*GD_)               // 307200
#define OUT_QS    (OUT_SCORE + T_*N_*N_) // 947200

#define ROWH 264                 // padded half-row stride for k_pair ldmatrix tiles

__device__ __half g_ABh[TNROWS*H0_];     // fp16(A + b1)
__device__ __half g_Bh [TNROWS*H0_];     // fp16(B)
__device__ __half g_W2h[H1_*H0_];        // fp16(fc1_w2)
__device__ __half g_ladjH[T_*N_*N_];     // fp16(learned_adj)
__device__ __half g_supH[TNROWS*GD_];
__device__ __half g_supL[TNROWS*GD_];
__device__ float  g_wl[TNROWS*GD_];
__device__ float  g_h2a[TNROWS*H1_];
__device__ float  g_h2b[TNROWS*H1_];

__device__ __forceinline__ float sigmoidf_(float x){ return 1.0f/(1.0f + __expf(-x)); }

__device__ __forceinline__ unsigned smem_u32(const void* p){
    unsigned a;
    asm("{ .reg .u64 t; cvta.to.shared.u64 t, %1; cvt.u32.u64 %0, t; }" : "=r"(a) : "l"(p));
    return a;
}
__device__ __forceinline__ void ldsm_x4(unsigned* r, unsigned addr){
    asm volatile("ldmatrix.sync.aligned.m8n8.x4.shared.b16 {%0,%1,%2,%3}, [%4];"
        : "=r"(r[0]), "=r"(r[1]), "=r"(r[2]), "=r"(r[3]) : "r"(addr));
}
__device__ __forceinline__ void ldsm_x4_t(unsigned* r, unsigned addr){
    asm volatile("ldmatrix.sync.aligned.m8n8.x4.trans.shared.b16 {%0,%1,%2,%3}, [%4];"
        : "=r"(r[0]), "=r"(r[1]), "=r"(r[2]), "=r"(r[3]) : "r"(addr));
}
__device__ __forceinline__ void mma16816(float* d, const unsigned* a, const unsigned* b){
    asm volatile("mma.sync.aligned.m16n8k16.row.col.f32.f16.f16.f32 "
        "{%0,%1,%2,%3},{%4,%5,%6,%7},{%8,%9},{%0,%1,%2,%3};"
        : "+f"(d[0]), "+f"(d[1]), "+f"(d[2]), "+f"(d[3])
        : "r"(a[0]), "r"(a[1]), "r"(a[2]), "r"(a[3]), "r"(b[0]), "r"(b[1]));
}
__device__ __forceinline__ void split2(float x, __half& h, __half& l){
    h = __float2half_rn(x);
    l = __float2half_rn(x - __half2float(h));
}
__device__ __forceinline__ void mma_m16n32_t(float d[4][4], unsigned Asu, unsigned Bsu,
                                             int lane, int warp_m, int warp_n, int PA, int PB)
{
    int ar = lane & 15, ac = (lane >> 4) * 8;
    int bk = ((lane >> 3) & 1) * 8 + (lane & 7);
    int bj = ((lane >> 4) & 1) * 8;
    #pragma unroll
    for (int ks = 0; ks < 4; ks++){
        unsigned a[4], b[2][4];
        ldsm_x4(a, Asu + (unsigned)(((warp_m*16 + ar)*PA + ks*16 + ac)*2));
        #pragma unroll
        for (int nb = 0; nb < 2; nb++)
            ldsm_x4_t(b[nb], Bsu + (unsigned)(((ks*16 + bk)*PB + warp_n*32 + nb*16 + bj)*2));
        #pragma unroll
        for (int nb = 0; nb < 2; nb++){
            mma16816(d[nb*2+0], a, &b[nb][0]);
            mma16816(d[nb*2+1], a, &b[nb][2]);
        }
    }
}
__device__ __forceinline__ void mma_m16n32_n(float d[4][4], unsigned Asu, unsigned Bsu,
                                             int lane, int warp_m, int warp_n, int PA, int PB)
{
    int ar = lane & 15, ac = (lane >> 4) * 8;
    int bg = lane >> 3;
    int bj = ((bg >= 2) ? 8 : 0) + (lane & 7);
    int bk2 = (bg & 1) * 8;
    #pragma unroll
    for (int ks = 0; ks < 4; ks++){
        unsigned a[4], b[2][4];
        ldsm_x4(a, Asu + (unsigned)(((warp_m*16 + ar)*PA + ks*16 + ac)*2));
        #pragma unroll
        for (int nb = 0; nb < 2; nb++)
            ldsm_x4(b[nb], Bsu + (unsigned)(((warp_n*32 + nb*16 + bj)*PB + ks*16 + bk2)*2));
        #pragma unroll
        for (int nb = 0; nb < 2; nb++){
            mma16816(d[nb*2+0], a, &b[nb][0]);
            mma16816(d[nb*2+1], a, &b[nb][2]);
        }
    }
}

// ---------------------------------------------------------------------------
// Kernel 1: A/B precompute (GEMM, fp32 SIMT) -> fp16 g_ABh (A+b1), g_Bh
// ---------------------------------------------------------------------------
__global__ void k_pre(const float* __restrict__ nf, const float* __restrict__ w1,
                      const float* __restrict__ b1)
{
    __shared__ float As[16][64];
    __shared__ float Bs[16][64];
    int tid = threadIdx.x;
    int m0 = blockIdx.y*64, h0 = blockIdx.x*64;
    int tx = tid & 15, ty = tid >> 4;
    float acc[4][4] = {};
    for (int k0 = 0; k0 < D_; k0 += 16){
        #pragma unroll
        for (int i = 0; i < 4; i++){
            int e = i*256 + tid;
            int r = e >> 4, kk = e & 15;
            As[kk][r] = nf[(m0 + r)*D_ + k0 + kk];
        }
        {
            int o  = tid >> 2;
            int kq = (tid & 3)*4;
            int hp = h0 + o;
            const float* src = w1 + (hp & 255)*(2*D_) + (hp >> 8)*D_ + k0 + kq;
            float4 w = *(const float4*)src;
            Bs[kq+0][o] = w.x; Bs[kq+1][o] = w.y; Bs[kq+2][o] = w.z; Bs[kq+3][o] = w.w;
        }
        __syncthreads();
        #pragma unroll
        for (int kk = 0; kk < 16; kk++){
            float ra[4], rb[4];
            #pragma unroll
            for (int i = 0; i < 4; i++) ra[i] = As[kk][ty*4 + i];
            #pragma unroll
            for (int jj = 0; jj < 4; jj++) rb[jj] = Bs[kk][tx*4 + jj];
            #pragma unroll
            for (int i = 0; i < 4; i++)
                #pragma unroll
                for (int jj = 0; jj < 4; jj++)
                    acc[i][jj] += ra[i]*rb[jj];
        }
        __syncthreads();
    }
    #pragma unroll
    for (int i = 0; i < 4; i++)
        #pragma unroll
        for (int jj = 0; jj < 4; jj++){
            int hp = h0 + tx*4 + jj;
            int row = m0 + ty*4 + i;
            float v = acc[i][jj];
            if (hp < H0_) g_ABh[row*H0_ + hp]         = __float2half_rn(v + b1[hp]);
            else          g_Bh [row*H0_ + (hp - 256)] = __float2half_rn(v);
        }
}

// ---------------------------------------------------------------------------
// Kernel 1b: W2 -> fp16 once
// ---------------------------------------------------------------------------
__global__ void k_w2h(const float* __restrict__ w2)
{
    int i = blockIdx.x*256 + threadIdx.x;
    if (i < H1_*H0_) g_W2h[i] = __float2half_rn(w2[i]);
}

// ---------------------------------------------------------------------------
// Kernel 2: pairwise MLP (R12 exact: 2 'a' rows/block, shared raw-B tile,
// m16 tail for b0=384)
// ---------------------------------------------------------------------------
__global__ void __launch_bounds__(256, 1)
k_pair(const float* __restrict__ b2v, const float* __restrict__ w3,
       const float* __restrict__ b3v, float* __restrict__ score_out)
{
    extern __shared__ char smraw[];
    __half* h1s = (__half*)smraw;                 // 128*ROWH
    __half* W2s = h1s + 128*ROWH;                 // 128*ROWH
    __half* rBs = W2s + 128*ROWH;                 // 128*ROWH (raw B tile)
    __half* Ar0 = rBs + 128*ROWH;                 // 256
    __half* Ar1 = Ar0 + H0_;                      // 256
    float*  sred = (float*)(Ar1 + H0_);           // 128
    float*  b2s  = sred + H1_;                    // 128
    float*  w3s  = b2s + H1_;                     // 128

    int a0 = blockIdx.x*2, a1 = a0 + 1;
    int t  = a0 / N_;
    int tid = threadIdx.x, lane = tid & 31, wid = tid >> 5;
    int warp_n = wid & 3, warp_m = wid >> 2;

    #pragma unroll
    for (int i = 0; i < 16; i++){
        int idx = i*256 + tid;
        int row = idx >> 5, c8 = idx & 31;
        *(uint4*)&W2s[row*ROWH + c8*8] = *(const uint4*)&g_W2h[row*H0_ + c8*8];
    }
    Ar0[tid] = g_ABh[a0*H0_ + tid];
    Ar1[tid] = g_ABh[a1*H0_ + tid];
    if (tid < H1_){ b2s[tid] = b2v[tid]; w3s[tid] = w3[tid]; }
    float b3 = b3v[0];

    unsigned h1u = smem_u32(h1s);
    unsigned w2u = smem_u32(W2s);

    int a_trow  = lane & 15;
    int a_tcol8 = (lane >> 4) * 8;
    int b_g     = lane >> 3;
    int b_joff  = ((b_g >= 2) ? 8 : 0) + (lane & 7);
    int b_koff  = (b_g & 1) * 8;

    unsigned aA[4], bA[2];
    #pragma unroll
    for (int mt = 0; mt < 4; mt++)
        aA[mt] = h1u + ((warp_m*64 + mt*16 + a_trow)*ROWH + a_tcol8)*2;
    #pragma unroll
    for (int nb = 0; nb < 2; nb++)
        bA[nb] = w2u + ((warp_n*32 + nb*16 + b_joff)*ROWH + b_koff)*2;

    const __half2 z2 = __float2half2_rn(0.f);

    for (int b0 = 0; b0 < 384; b0 += 128){
        __syncthreads();
        #pragma unroll
        for (int i = 0; i < 16; i++){
            int idx = i*256 + tid;
            int row = idx >> 5, c8 = idx & 31;
            uint4 v = *(const uint4*)&g_Bh[((size_t)(t*N_ + b0 + row))*H0_ + c8*8];
            *(uint4*)&rBs[row*ROWH + c8*8] = v;
            const __half2* vp = (const __half2*)&v;
            uint4 o; __half2* op = (__half2*)&o;
            #pragma unroll
            for (int q = 0; q < 4; q++)
                op[q] = __hmax2(__hadd2(vp[q], *(const __half2*)&Ar0[c8*8 + q*2]), z2);
            *(uint4*)&h1s[row*ROWH + c8*8] = o;
        }
        if (tid < H1_) sred[tid] = 0.f;
        __syncthreads();

        {
            float d[4][4][4];
            #pragma unroll
            for (int i=0;i<4;i++)
                #pragma unroll
                for (int j=0;j<4;j++)
                    #pragma unroll
                    for (int v=0;v<4;v++) d[i][j][v]=0.f;
            #pragma unroll 4
            for (int ks = 0; ks < 16; ks++){
                unsigned afr[4][4], bfr[2][4];
                #pragma unroll
                for (int mt = 0; mt < 4; mt++) ldsm_x4(afr[mt], aA[mt] + ks*32);
                #pragma unroll
                for (int nb = 0; nb < 2; nb++) ldsm_x4(bfr[nb], bA[nb] + ks*32);
                #pragma unroll
                for (int mt = 0; mt < 4; mt++)
                    #pragma unroll
                    for (int nb = 0; nb < 2; nb++){
                        mma16816(d[mt][nb*2+0], afr[mt], &bfr[nb][0]);
                        mma16816(d[mt][nb*2+1], afr[mt], &bfr[nb][2]);
                    }
            }
            #pragma unroll
            for (int mt = 0; mt < 4; mt++){
                #pragma unroll
                for (int h = 0; h < 2; h++){
                    float part = 0.f;
                    #pragma unroll
                    for (int n8 = 0; n8 < 4; n8++){
                        #pragma unroll
                        for (int c = 0; c < 2; c++){
                            int j = warp_n*32 + n8*8 + (lane & 3)*2 + c;
                            part += fmaxf(d[mt][n8][h*2 + c] + b2s[j], 0.f) * w3s[j];
                        }
                    }
                    part += __shfl_xor_sync(0xffffffff, part, 1);
                    part += __shfl_xor_sync(0xffffffff, part, 2);
                    if ((lane & 3) == 0)
                        atomicAdd(&sred[warp_m*64 + mt*16 + (lane >> 2) + h*8], part);
                }
            }
        }
        __syncthreads();
        if (tid < H1_){
            score_out[a0*N_ + b0 + tid] = sigmoidf_(sred[tid] + b3);
            sred[tid] = 0.f;
        }
        #pragma unroll
        for (int i = 0; i < 16; i++){
            int idx = i*256 + tid;
            int row = idx >> 5, c8 = idx & 31;
            uint4 v = *(const uint4*)&rBs[row*ROWH + c8*8];
            const __half2* vp = (const __half2*)&v;
            uint4 o; __half2* op = (__half2*)&o;
            #pragma unroll
            for (int q = 0; q < 4; q++)
                op[q] = __hmax2(__hadd2(vp[q], *(const __half2*)&Ar1[c8*8 + q*2]), z2);
            *(uint4*)&h1s[row*ROWH + c8*8] = o;
        }
        __syncthreads();

        {
            float d[4][4][4];
            #pragma unroll
            for (int i=0;i<4;i++)
                #pragma unroll
                for (int j=0;j<4;j++)
                    #pragma unroll
                    for (int v=0;v<4;v++) d[i][j][v]=0.f;
            #pragma unroll 4
            for (int ks = 0; ks < 16; ks++){
                unsigned afr[4][4], bfr[2][4];
                #pragma unroll
                for (int mt = 0; mt < 4; mt++) ldsm_x4(afr[mt], aA[mt] + ks*32);
                #pragma unroll
                for (int nb = 0; nb < 2; nb++) ldsm_x4(bfr[nb], bA[nb] + ks*32);
                #pragma unroll
                for (int mt = 0; mt < 4; mt++)
                    #pragma unroll
                    for (int nb = 0; nb < 2; nb++){
                        mma16816(d[mt][nb*2+0], afr[mt], &bfr[nb][0]);
                        mma16816(d[mt][nb*2+1], afr[mt], &bfr[nb][2]);
                    }
            }
            #pragma unroll
            for (int mt = 0; mt < 4; mt++){
                #pragma unroll
                for (int h = 0; h < 2; h++){
                    float part = 0.f;
                    #pragma unroll
                    for (int n8 = 0; n8 < 4; n8++){
                        #pragma unroll
                        for (int c = 0; c < 2; c++){
                            int j = warp_n*32 + n8*8 + (lane & 3)*2 + c;
                            part += fmaxf(d[mt][n8][h*2 + c] + b2s[j], 0.f) * w3s[j];
                        }
                    }
                    part += __shfl_xor_sync(0xffffffff, part, 1);
                    part += __shfl_xor_sync(0xffffffff, part, 2);
                    if ((lane & 3) == 0)
                        atomicAdd(&sred[warp_m*64 + mt*16 + (lane >> 2) + h*8], part);
                }
            }
        }
        __syncthreads();
        if (tid < H1_)
            score_out[a1*N_ + b0 + tid] = sigmoidf_(sred[tid] + b3);
    }

    // tail tile b0 = 384 (16 rows)
    {
        const int b0 = 384;
        __syncthreads();
        #pragma unroll
        for (int i = 0; i < 2; i++){
            int idx = i*256 + tid;
            int row = idx >> 5, c8 = idx & 31;
            uint4 v = *(const uint4*)&g_Bh[((size_t)(t*N_ + b0 + row))*H0_ + c8*8];
            *(uint4*)&rBs[row*ROWH + c8*8] = v;
            const __half2* vp = (const __half2*)&v;
            uint4 o; __half2* op = (__half2*)&o;
            #pragma unroll
            for (int q = 0; q < 4; q++)
                op[q] = __hmax2(__hadd2(vp[q], *(const __half2*)&Ar0[c8*8 + q*2]), z2);
            *(uint4*)&h1s[row*ROWH + c8*8] = o;
        }
        if (tid < H1_) sred[tid] = 0.f;
        __syncthreads();

        if (warp_m == 0){
            float d[4][4];
            #pragma unroll
            for (int j=0;j<4;j++)
                #pragma unroll
                for (int v=0;v<4;v++) d[j][v]=0.f;
            #pragma unroll 4
            for (int ks = 0; ks < 16; ks++){
                unsigned afr[4], bfr[2][4];
                ldsm_x4(afr, h1u + ((a_trow)*ROWH + a_tcol8)*2 + ks*32);
                #pragma unroll
                for (int nb = 0; nb < 2; nb++) ldsm_x4(bfr[nb], bA[nb] + ks*32);
                #pragma unroll
                for (int nb = 0; nb < 2; nb++){
                    mma16816(d[nb*2+0], afr, &bfr[nb][0]);
                    mma16816(d[nb*2+1], afr, &bfr[nb][2]);
                }
            }
            #pragma unroll
            for (int h = 0; h < 2; h++){
                float part = 0.f;
                #pragma unroll
                for (int n8 = 0; n8 < 4; n8++){
                    #pragma unroll
                    for (int c = 0; c < 2; c++){
                        int j = warp_n*32 + n8*8 + (lane & 3)*2 + c;
                        part += fmaxf(d[n8][h*2 + c] + b2s[j], 0.f) * w3s[j];
                    }
                }
                part += __shfl_xor_sync(0xffffffff, part, 1);
                part += __shfl_xor_sync(0xffffffff, part, 2);
                if ((lane & 3) == 0)
                    atomicAdd(&sred[(lane >> 2) + h*8], part);
            }
        }
        __syncthreads();
        if (tid < 16)
            score_out[a0*N_ + b0 + tid] = sigmoidf_(sred[tid] + b3);
        if (tid < H1_) sred[tid] = 0.f;
        #pragma unroll
        for (int i = 0; i < 2; i++){
            int idx = i*256 + tid;
            int row = idx >> 5, c8 = idx & 31;
            uint4 v = *(const uint4*)&rBs[row*ROWH + c8*8];
            const __half2* vp = (const __half2*)&v;
            uint4 o; __half2* op = (__half2*)&o;
            #pragma unroll
            for (int q = 0; q < 4; q++)
                op[q] = __hmax2(__hadd2(vp[q], *(const __half2*)&Ar1[c8*8 + q*2]), z2);
            *(uint4*)&h1s[row*ROWH + c8*8] = o;
        }
        __syncthreads();

        if (warp_m == 0){
            float d[4][4];
            #pragma unroll
            for (int j=0;j<4;j++)
                #pragma unroll
                for (int v=0;v<4;v++) d[j][v]=0.f;
            #pragma unroll 4
            for (int ks = 0; ks < 16; ks++){
                unsigned afr[4], bfr[2][4];
                ldsm_x4(afr, h1u + ((a_trow)*ROWH + a_tcol8)*2 + ks*32);
                #pragma unroll
                for (int nb = 0; nb < 2; nb++) ldsm_x4(bfr[nb], bA[nb] + ks*32);
                #pragma unroll
                for (int nb = 0; nb < 2; nb++){
                    mma16816(d[nb*2+0], afr, &bfr[nb][0]);
                    mma16816(d[nb*2+1], afr, &bfr[nb][2]);
                }
            }
            #pragma unroll
            for (int h = 0; h < 2; h++){
                float part = 0.f;
                #pragma unroll
                for (int n8 = 0; n8 < 4; n8++){
                    #pragma unroll
                    for (int c = 0; c < 2; c++){
                        int j = warp_n*32 + n8*8 + (lane & 3)*2 + c;
                        part += fmaxf(d[n8][h*2 + c] + b2s[j], 0.f) * w3s[j];
                    }
                }
                part += __shfl_xor_sync(0xffffffff, part, 1);
                part += __shfl_xor_sync(0xffffffff, part, 2);
                if ((lane & 3) == 0)
                    atomicAdd(&sred[(lane >> 2) + h*8], part);
            }
        }
        __syncthreads();
        if (tid < 16)
            score_out[a1*N_ + b0 + tid] = sigmoidf_(sred[tid] + b3);
    }
}

// ---------------------------------------------------------------------------
// Kernel 2b: learned_adj -> fp16
// ---------------------------------------------------------------------------
__global__ void k_ladj(const float* __restrict__ adj, const float* __restrict__ score)
{
    int idx = blockIdx.x*256 + threadIdx.x;
    if (idx >= T_*N_*N_) return;
    int t = idx / (N_*N_);
    int r = idx % (N_*N_);
    int n = r / N_, m = r % N_;
    float v = score[idx];
    if (n < S_ && m < S_)
        v = (adj[(t*S_ + n)*S_ + m] > 0.f) ? 1.f : -v;
    g_ladjH[idx] = __float2half_rn(v);
}

// ---------------------------------------------------------------------------
// Kernel 3: support (hi/lo split, 3 passes), 64x64 tiles
// ---------------------------------------------------------------------------
__global__ void __launch_bounds__(256)
k_support(const float* __restrict__ nf, const float* __restrict__ Wg)
{
    __shared__ __align__(16) __half Ah[64*72];
    __shared__ __align__(16) __half Al[64*72];
    __shared__ __align__(16) __half Bh[64*72];
    __shared__ __align__(16) __half Bl[64*72];
    int tid = threadIdx.x, lane = tid & 31, wid = tid >> 5;
    int warp_m = wid >> 1, warp_n = wid & 1;
    int o0 = blockIdx.x*64, m0 = blockIdx.y*64;
    unsigned Ahu = smem_u32(Ah), Alu = smem_u32(Al);
    unsigned Bhu = smem_u32(Bh), Blu = smem_u32(Bl);
    float d[4][4] = {};

    for (int k0 = 0; k0 < GD_; k0 += 64){
        #pragma unroll
        for (int i = 0; i < 4; i++){
            int idx = i*256 + tid;
            int row = idx >> 4, c4 = idx & 15;
            int m = m0 + row, f = k0 + c4*4;
            float4 v = make_float4(0.f,0.f,0.f,0.f);
            if (m < TNROWS){
                int tt = m / N_, n = m % N_;
                int node = (f < D_) ? n : (S_ + (f >> 7) - 1);
                v = *(const float4*)&nf[(tt*N_ + node)*D_ + (f & 127)];
            }
            __half h0,l0,h1,l1,h2,l2,h3,l3;
            split2(v.x,h0,l0); split2(v.y,h1,l1); split2(v.z,h2,l2); split2(v.w,h3,l3);
            *(__half2*)&Ah[row*72 + c4*4]     = __halves2half2(h0,h1);
            *(__half2*)&Ah[row*72 + c4*4 + 2] = __halves2half2(h2,h3);
            *(__half2*)&Al[row*72 + c4*4]     = __halves2half2(l0,l1);
            *(__half2*)&Al[row*72 + c4*4 + 2] = __halves2half2(l2,l3);
        }
        #pragma unroll
        for (int i = 0; i < 4; i++){
            int idx = i*256 + tid;
            int row = idx >> 4, c4 = idx & 15;
            float4 v = *(const float4*)&Wg[(k0 + row)*GD_ + o0 + c4*4];
            __half h0,l0,h1,l1,h2,l2,h3,l3;
            split2(v.x,h0,l0); split2(v.y,h1,l1); split2(v.z,h2,l2); split2(v.w,h3,l3);
            *(__half2*)&Bh[row*72 + c4*4]     = __halves2half2(h0,h1);
            *(__half2*)&Bh[row*72 + c4*4 + 2] = __halves2half2(h2,h3);
            *(__half2*)&Bl[row*72 + c4*4]     = __halves2half2(l0,l1);
            *(__half2*)&Bl[row*72 + c4*4 + 2] = __halves2half2(l2,l3);
        }
        __syncthreads();
        mma_m16n32_t(d, Ahu, Bhu, lane, warp_m, warp_n, 72, 72);
        mma_m16n32_t(d, Ahu, Blu, lane, warp_m, warp_n, 72, 72);
        mma_m16n32_t(d, Alu, Bhu, lane, warp_m, warp_n, 72, 72);
        __syncthreads();
    }
    #pragma unroll
    for (int n8 = 0; n8 < 4; n8++)
        #pragma unroll
        for (int v = 0; v < 4; v++){
            int row = m0 + warp_m*16 + (lane >> 2) + (v >> 1)*8;
            int col = o0 + warp_n*32 + n8*8 + (lane & 3)*2 + (v & 1);
            if (row < TNROWS){
                __half h, l;
                split2(d[n8][v], h, l);
                g_supH[row*GD_ + col] = h;
                g_supL[row*GD_ + col] = l;
            }
        }
}

// ---------------------------------------------------------------------------
// Kernel 4: wl = relu(ladj·sup + biasG), 64x64 tiles, B hi+lo (2 passes)
// ---------------------------------------------------------------------------
__global__ void __launch_bounds__(256)
k_wl(const float* __restrict__ biasG)
{
    __shared__ __align__(16) __half As[64*72];
    __shared__ __align__(16) __half Bh[64*72];
    __shared__ __align__(16) __half Bl[64*72];
    int tid = threadIdx.x, lane = tid & 31, wid = tid >> 5;
    int warp_m = wid >> 1, warp_n = wid & 1;
    int o0 = blockIdx.x*64, m0 = blockIdx.y*64, t = blockIdx.z;
    unsigned Asu = smem_u32(As), Bhu = smem_u32(Bh), Blu = smem_u32(Bl);
    float d[4][4] = {};

    for (int k0 = 0; k0 < N_; k0 += 64){
        #pragma unroll
        for (int i = 0; i < 2; i++){
            int idx = i*256 + tid;
            int row = idx >> 3, c8 = idx & 7;
            int n = m0 + row, k = k0 + c8*8;
            uint4 v = make_uint4(0u,0u,0u,0u);
            if (n < N_ && k < N_)
                v = *(const uint4*)&g_ladjH[(t*N_ + n)*N_ + k];
            *(uint4*)&As[row*72 + c8*8] = v;
        }
        #pragma unroll
        for (int i = 0; i < 2; i++){
            int idx = i*256 + tid;
            int row = idx >> 3, c8 = idx & 7;
            int k = k0 + row;
            uint4 vh = make_uint4(0u,0u,0u,0u);
            uint4 vl = make_uint4(0u,0u,0u,0u);
            if (k < N_){
                vh = *(const uint4*)&g_supH[(t*N_ + k)*GD_ + o0 + c8*8];
                vl = *(const uint4*)&g_supL[(t*N_ + k)*GD_ + o0 + c8*8];
            }
            *(uint4*)&Bh[row*72 + c8*8] = vh;
            *(uint4*)&Bl[row*72 + c8*8] = vl;
        }
        __syncthreads();
        mma_m16n32_t(d, Asu, Bhu, lane, warp_m, warp_n, 72, 72);
        mma_m16n32_t(d, Asu, Blu, lane, warp_m, warp_n, 72, 72);
        __syncthreads();
    }
    #pragma unroll
    for (int n8 = 0; n8 < 4; n8++)
        #pragma unroll
        for (int v = 0; v < 4; v++){
            int n = m0 + warp_m*16 + (lane >> 2) + (v >> 1)*8;
            int o = o0 + warp_n*32 + n8*8 + (lane & 3)*2 + (v & 1);
            if (n < N_)
                g_wl[(t*N_ + n)*GD_ + o] = fmaxf(d[n8][v] + biasG[o], 0.f);
        }
}

// ---------------------------------------------------------------------------
// Kernel 5: wl mean over t -> out[0 .. 307200)
// ---------------------------------------------------------------------------
__global__ void k_mean(float* __restrict__ out)
{
    int i = blockIdx.x*blockDim.x + threadIdx.x;
    if (i < N_*GD_){
        float s = g_wl[i] + g_wl[i + N_*GD_] + g_wl[i + 2*N_*GD_] + g_wl[i + 3*N_*GD_];
        out[i] = 0.25f * s;
    }
}

// ---------------------------------------------------------------------------
// Kernel 6: h2a = relu(wl·W1^T + b1), hi/lo split MMA (3 passes), 64x64 tiles
// ---------------------------------------------------------------------------
__global__ void __launch_bounds__(256)
k_fc2a(const float* __restrict__ W, const float* __restrict__ bias)
{
    __shared__ __align__(16) __half Ah[64*72];
    __shared__ __align__(16) __half Al[64*72];
    __shared__ __align__(16) __half Bh[64*72];
    __shared__ __align__(16) __half Bl[64*72];
    int tid = threadIdx.x, lane = tid & 31, wid = tid >> 5;
    int warp_m = wid >> 1, warp_n = wid & 1;
    int o0 = blockIdx.x*64, m0 = blockIdx.y*64;
    unsigned Ahu = smem_u32(Ah), Alu = smem_u32(Al);
    unsigned Bhu = smem_u32(Bh), Blu = smem_u32(Bl);
    float d[4][4] = {};

    for (int k0 = 0; k0 < GD_; k0 += 64){
        #pragma unroll
        for (int i = 0; i < 4; i++){
            int idx = i*256 + tid;
            int row = idx >> 4, c4 = idx & 15;
            int m = m0 + row;
            float4 v = make_float4(0.f,0.f,0.f,0.f);
            if (m < TNROWS) v = *(const float4*)&g_wl[m*GD_ + k0 + c4*4];
            __half h0,l0,h1,l1,h2,l2,h3,l3;
            split2(v.x,h0,l0); split2(v.y,h1,l1); split2(v.z,h2,l2); split2(v.w,h3,l3);
            *(__half2*)&Ah[row*72 + c4*4]     = __halves2half2(h0,h1);
            *(__half2*)&Ah[row*72 + c4*4 + 2] = __halves2half2(h2,h3);
            *(__half2*)&Al[row*72 + c4*4]     = __halves2half2(l0,l1);
            *(__half2*)&Al[row*72 + c4*4 + 2] = __halves2half2(l2,l3);
        }
        #pragma unroll
        for (int i = 0; i < 4; i++){
            int idx = i*256 + tid;
            int row = idx >> 4, c4 = idx & 15;      // row = j (output neuron)
            float4 v = *(const float4*)&W[(o0 + row)*GD_ + k0 + c4*4];
            __half h0,l0,h1,l1,h2,l2,h3,l3;
            split2(v.x,h0,l0); split2(v.y,h1,l1); split2(v.z,h2,l2); split2(v.w,h3,l3);
            *(__half2*)&Bh[row*72 + c4*4]     = __halves2half2(h0,h1);
            *(__half2*)&Bh[row*72 + c4*4 + 2] = __halves2half2(h2,h3);
            *(__half2*)&Bl[row*72 + c4*4]     = __halves2half2(l0,l1);
            *(__half2*)&Bl[row*72 + c4*4 + 2] = __halves2half2(l2,l3);
        }
        __syncthreads();
        mma_m16n32_n(d, Ahu, Bhu, lane, warp_m, warp_n, 72, 72);
        mma_m16n32_n(d, Ahu, Blu, lane, warp_m, warp_n, 72, 72);
        mma_m16n32_n(d, Alu, Bhu, lane, warp_m, warp_n, 72, 72);
        __syncthreads();
    }
    #pragma unroll
    for (int n8 = 0; n8 < 4; n8++)
        #pragma unroll
        for (int v = 0; v < 4; v++){
            int row = m0 + warp_m*16 + (lane >> 2) + (v >> 1)*8;
            int col = o0 + warp_n*32 + n8*8 + (lane & 3)*2 + (v & 1);
            if (row < TNROWS)
                g_h2a[row*H1_ + col] = fmaxf(d[n8][v] + bias[col], 0.f);
        }
}

// ---------------------------------------------------------------------------
// Kernel 7: h2b = relu(h2a·W2^T + b)  fp32 SIMT  M=1600,K=128,O=128
// ---------------------------------------------------------------------------
__global__ void k_fc2b(const float* __restrict__ W, const float* __restrict__ bias)
{
    __shared__ float As[16][64];
    __shared__ float Bs[16][64];
    int tid = threadIdx.x;
    int m0 = blockIdx.y*64, o0 = blockIdx.x*64;
    int tx = tid & 15, ty = tid >> 4;
    float acc[4][4] = {};
    for (int k0 = 0; k0 < H1_; k0 += 16){
        #pragma unroll
        for (int i = 0; i < 4; i++){
            int e = i*256 + tid;
            int r = e >> 4, kk = e & 15;
            As[kk][r] = g_h2a[(m0 + r)*H1_ + k0 + kk];
        }
        {
            int o  = tid >> 2;
            int kq = (tid & 3)*4;
            float4 w = *(const float4*)&W[(o0 + o)*H1_ + k0 + kq];
            Bs[kq+0][o] = w.x; Bs[kq+1][o] = w.y; Bs[kq+2][o] = w.z; Bs[kq+3][o] = w.w;
        }
        __syncthreads();
        #pragma unroll
        for (int kk = 0; kk < 16; kk++){
            float ra[4], rb[4];
            #pragma unroll
            for (int i = 0; i < 4; i++) ra[i] = As[kk][ty*4 + i];
            #pragma unroll
            for (int jj = 0; jj < 4; jj++) rb[jj] = Bs[kk][tx*4 + jj];
            #pragma unroll
            for (int i = 0; i < 4; i++)
                #pragma unroll
                for (int jj = 0; jj < 4; jj++)
                    acc[i][jj] += ra[i]*rb[jj];
        }
        __syncthreads();
    }
    #pragma unroll
    for (int i = 0; i < 4; i++)
        #pragma unroll
        for (int jj = 0; jj < 4; jj++){
            int o = o0 + tx*4 + jj;
            g_h2b[(m0 + ty*4 + i)*H1_ + o] = fmaxf(acc[i][jj] + bias[o], 0.f);
        }
}

// ---------------------------------------------------------------------------
// Kernel 8: query[t,c,n] = sigmoid( h2b[t,n,:]·w3[c,:] + b3[c] )
// ---------------------------------------------------------------------------
__global__ void k_query(const float* __restrict__ w3, const float* __restrict__ b3,
                        float* __restrict__ out)
{
    int idx = blockIdx.x*blockDim.x + threadIdx.x;
    if (idx >= TNROWS*5) return;
    int row = idx / 5, c = idx % 5;
    const float* h = g_h2b + row*H1_;
    const float* w = w3 + c*H1_;
    float s = 0.f;
    #pragma unroll 8
    for (int k = 0; k < H1_; k++) s += h[k]*w[k];
    int t = row / N_, n = row % N_;
    out[OUT_QS + t*5*N_ + c*N_ + n] = sigmoidf_(s + b3[c]);
}

// ---------------------------------------------------------------------------
extern "C" void kernel_launch(void* const* d_in, const int* in_sizes, int n_in,
                              void* d_out, int out_size)
{
    const float* nf       = (const float*)d_in[0];
    const float* adj      = (const float*)d_in[1];
    const float* fc1_w1   = (const float*)d_in[2];
    const float* fc1_b1   = (const float*)d_in[3];
    const float* fc1_w2   = (const float*)d_in[4];
    const float* fc1_b2   = (const float*)d_in[5];
    const float* fc1_w3   = (const float*)d_in[6];
    const float* fc1_b3   = (const float*)d_in[7];
    const float* weight_G = (const float*)d_in[8];
    const float* bias_G   = (const float*)d_in[9];
    const float* fc2_w1   = (const float*)d_in[10];
    const float* fc2_b1   = (const float*)d_in[11];
    const float* fc2_w2   = (const float*)d_in[12];
    const float* fc2_b2   = (const float*)d_in[13];
    const float* fc2_w3   = (const float*)d_in[14];
    const float* fc2_b3   = (const float*)d_in[15];

    float* out       = (float*)d_out;
    float* score_out = out + OUT_SCORE;

    // side stream + events, created once on the first (uncaptured) call.
    // Work is identical on every call; only resource creation is one-time.
    static cudaStream_t s1 = 0;
    static cudaEvent_t eFork = 0, eSup = 0, eWl = 0, eMean = 0;
    if (!s1){
        cudaStreamCreateWithFlags(&s1, cudaStreamNonBlocking);
        cudaEventCreateWithFlags(&eFork, cudaEventDisableTiming);
        cudaEventCreateWithFlags(&eSup,  cudaEventDisableTiming);
        cudaEventCreateWithFlags(&eWl,   cudaEventDisableTiming);
        cudaEventCreateWithFlags(&eMean, cudaEventDisableTiming);
    }

    size_t smem_pair = (size_t)(3*128*ROWH + 2*H0_)*sizeof(__half)
                     + (size_t)(3*H1_)*sizeof(float);
    cudaFuncSetAttribute(k_pair, cudaFuncAttributeMaxDynamicSharedMemorySize, (int)smem_pair);

    // fork: side stream runs k_support (depends only on inputs) under k_pair
    cudaEventRecord(eFork, 0);
    cudaStreamWaitEvent(s1, eFork, 0);
    k_support<<<dim3(GD_/64, (TNROWS + 63)/64), 256, 0, s1>>>(nf, weight_G);
    cudaEventRecord(eSup, s1);

    // main chain
    k_pre<<<dim3(8, 25), 256>>>(nf, fc1_w1, fc1_b1);
    k_w2h<<<(H1_*H0_ + 255)/256, 256>>>(fc1_w2);
    k_pair<<<TNROWS/2, 256, smem_pair>>>(fc1_b2, fc1_w3, fc1_b3, score_out);
    k_ladj<<<(T_*N_*N_ + 255)/256, 256>>>(adj, score_out);

    cudaStreamWaitEvent(0, eSup, 0);
    k_wl<<<dim3(GD_/64, (N_ + 63)/64, T_), 256>>>(bias_G);
    cudaEventRecord(eWl, 0);

    // mean on side stream (depends only on k_wl; writes disjoint out region)
    cudaStreamWaitEvent(s1, eWl, 0);
    k_mean<<<(N_*GD_ + 255)/256, 256, 0, s1>>>(out);
    cudaEventRecord(eMean, s1);

    k_fc2a<<<dim3(H1_/64, (TNROWS + 63)/64), 256>>>(fc2_w1, fc2_b1);
    k_fc2b<<<dim3(H1_/64, TNROWS/64), 256>>>(fc2_w2, fc2_b2);
    k_query<<<(TNROWS*5 + 127)/128, 128>>>(fc2_w3, fc2_b3, out);

    cudaStreamWaitEvent(0, eMean, 0);   // join side stream before capture ends
}